// round 9
// baseline (speedup 1.0000x reference)
#include <cuda_runtime.h>
#include <cuda_fp16.h>
#include <math.h>

#define B_  256
#define T_  512
#define S_  64
#define O_  128
#define H_  128
#define G4  512   // 4*H
#define BT_ ((size_t)B_ * T_)

// ---------------- scratch (device globals; no runtime allocation) ----------
__device__ __half g_gzh[BT_ * G4];         // 134 MB : obs@K + b (half)
__device__ __half g_hsh[BT_ * H_];         // 33.5 MB LSTM hidden (half)
__device__ __half g_pmh[BT_ * S_];         // 16.8 MB posterior mean (half)
__device__ float  g_ps [BT_ * S_];         // 33.5 MB posterior scale (fp32)
__device__ __half g_KTh [512 * 128];       // K^T  (n-major)
__device__ __half g_RTh [512 * 128];       // R^T  (n-major, for tensor lstm)
__device__ __half g_WrTh[128 * 128];       // [Wrm|Wrs]^T (n-major, n<64 mean)
__device__ __half g_WgTh[256 * 64];        // [Wgm|Wgs]^T (n-major, n<128 mean)
__device__ float  g_cp[7][65][65];         // Aug^(64j), j=1..7
__device__ double g_acc[2];                // [0]=KL sum, [1]=recon-logp sum

__device__ __forceinline__ float softplusf_(float x) {
    return fmaxf(x, 0.f) + __logf(1.f + __expf(-fabsf(x)));
}
__device__ __forceinline__ float tanha_(float x) {
    float y; asm("tanh.approx.f32 %0, %1;" : "=f"(y) : "f"(x)); return y;
}
__device__ __forceinline__ float sigt_(float x) {   // sigmoid via MUFU.TANH
    return fmaf(tanha_(0.5f * x), 0.5f, 0.5f);
}

__device__ __forceinline__ void mma16816(float* c, const unsigned* a, const unsigned* b) {
    asm volatile(
        "mma.sync.aligned.m16n8k16.row.col.f32.f16.f16.f32 "
        "{%0,%1,%2,%3}, {%4,%5,%6,%7}, {%8,%9}, {%0,%1,%2,%3};\n"
        : "+f"(c[0]), "+f"(c[1]), "+f"(c[2]), "+f"(c[3])
        : "r"(a[0]), "r"(a[1]), "r"(a[2]), "r"(a[3]), "r"(b[0]), "r"(b[1]));
}
__device__ __forceinline__ void ldsm4(unsigned* a, unsigned addr) {
    asm volatile("ldmatrix.sync.aligned.m8n8.x4.shared.b16 {%0,%1,%2,%3}, [%4];\n"
                 : "=r"(a[0]), "=r"(a[1]), "=r"(a[2]), "=r"(a[3]) : "r"(addr));
}

// ---------------------------------------------------------------------------
__global__ void k_zero() { if (threadIdx.x < 2) g_acc[threadIdx.x] = 0.0; }

// weight transposes/concats -> half
__global__ void k_prep_w(const float* __restrict__ K,  const float* __restrict__ R,
                         const float* __restrict__ Wrm, const float* __restrict__ Wrs,
                         const float* __restrict__ Wgm, const float* __restrict__ Wgs) {
    int stride = gridDim.x * blockDim.x;
    for (int i = blockIdx.x * blockDim.x + threadIdx.x; i < 163840; i += stride) {
        if (i < 65536) {
            int n = i >> 7, k = i & 127;
            g_KTh[i] = __float2half(K[k * 512 + n]);
        } else if (i < 81920) {
            int j = i - 65536; int n = j >> 7, k = j & 127;
            float v = (n < 64) ? Wrm[k * 64 + n] : Wrs[k * 64 + (n - 64)];
            g_WrTh[j] = __float2half(v);
        } else if (i < 98304) {
            int j = i - 81920; int n = j >> 6, k = j & 63;
            float v = (n < 128) ? Wgm[k * 128 + n] : Wgs[k * 128 + (n - 128)];
            g_WgTh[j] = __float2half(v);
        } else {
            int j = i - 98304; int n = j >> 7, k = j & 127;
            g_RTh[j] = __float2half(R[k * 512 + n]);
        }
    }
}

// ---------------------------------------------------------------------------
// Aug = [[Wfm, 0],[bfm, 1]] (65x65, row-vector convention).
#define PW_N  65
#define PW_LD 66
__global__ __launch_bounds__(256) void k_powers(const float* __restrict__ Wfm,
                                                const float* __restrict__ bfm) {
    __shared__ float A[PW_N * PW_LD];
    __shared__ float Cur[PW_N * PW_LD];
    const int tid = threadIdx.x;

    for (int i = tid; i < PW_N * PW_N; i += 256) {
        int r = i / PW_N, s = i % PW_N;
        float v;
        if (r < 64 && s < 64)      v = Wfm[r * 64 + s];
        else if (r == 64 && s < 64) v = bfm[s];
        else                        v = (r == 64 && s == 64) ? 1.f : 0.f;
        A[r * PW_LD + s] = v;
    }
    __syncthreads();

    float regs[17];
    #pragma unroll 1
    for (int d = 0; d < 6; d++) {          // A <- A*A, 6x  => Aug^64
        int c = 0;
        for (int i = tid; i < PW_N * PW_N; i += 256, c++) {
            int r = i / PW_N, s = i % PW_N;
            float acc = 0.f;
            for (int k = 0; k < PW_N; k++) acc += A[r * PW_LD + k] * A[k * PW_LD + s];
            regs[c] = acc;
        }
        __syncthreads();
        c = 0;
        for (int i = tid; i < PW_N * PW_N; i += 256, c++)
            A[(i / PW_N) * PW_LD + i % PW_N] = regs[c];
        __syncthreads();
    }
    for (int i = tid; i < PW_N * PW_N; i += 256) {
        int r = i / PW_N, s = i % PW_N;
        float v = A[r * PW_LD + s];
        Cur[r * PW_LD + s] = v;
        g_cp[0][r][s] = v;
    }
    __syncthreads();
    #pragma unroll 1
    for (int j = 2; j <= 7; j++) {         // Cur <- Cur*A  => Aug^(64j)
        int c = 0;
        for (int i = tid; i < PW_N * PW_N; i += 256, c++) {
            int r = i / PW_N, s = i % PW_N;
            float acc = 0.f;
            for (int k = 0; k < PW_N; k++) acc += Cur[r * PW_LD + k] * A[k * PW_LD + s];
            regs[c] = acc;
        }
        __syncthreads();
        c = 0;
        for (int i = tid; i < PW_N * PW_N; i += 256, c++) {
            int r = i / PW_N, s = i % PW_N;
            Cur[r * PW_LD + s] = regs[c];
            g_cp[j - 1][r][s] = regs[c];
        }
        __syncthreads();
    }
}

// ---------------------------------------------------------------------------
// gz = obs @ K + b via HMMA, output half, smem-staged coalesced stores.
__global__ __launch_bounds__(256) void k_xk(const float* __restrict__ obs,
                                            const float* __restrict__ bl) {
    extern __shared__ __half sm[];
    __half* As = sm;                 // [128][136]
    __half* Bt = sm + 128 * 136;     // [128][136]  (K^T tile / later C staging)
    const int tid = threadIdx.x;
    const int bt0 = blockIdx.y * 128;
    const int c0  = blockIdx.x * 128;

    const float4* ap = (const float4*)(obs + (size_t)bt0 * 128);
    #pragma unroll
    for (int i = tid; i < 128 * 32; i += 256) {
        int r = i >> 5, c = i & 31;
        float4 v = ap[r * 32 + c];
        *(half2*)&As[r * 136 + c * 4]     = __floats2half2_rn(v.x, v.y);
        *(half2*)&As[r * 136 + c * 4 + 2] = __floats2half2_rn(v.z, v.w);
    }
    const uint4* bp = (const uint4*)(g_KTh + (size_t)c0 * 128);
    #pragma unroll
    for (int i = tid; i < 128 * 16; i += 256) {
        int r = i >> 4, c = i & 15;
        *(uint4*)&Bt[r * 136 + c * 8] = bp[r * 16 + c];
    }
    __syncthreads();

    const int w = tid >> 5, l = tid & 31, g = l >> 2, tg = l & 3;
    const int m0 = w * 16;
    float acc[16][4];
    #pragma unroll
    for (int i = 0; i < 16; i++)
        #pragma unroll
        for (int j = 0; j < 4; j++) acc[i][j] = 0.f;

    #pragma unroll
    for (int kk = 0; kk < 8; kk++) {
        const int kb = kk * 16 + tg * 2;
        unsigned a[4];
        a[0] = *(const unsigned*)&As[(m0 + g)     * 136 + kb];
        a[1] = *(const unsigned*)&As[(m0 + g + 8) * 136 + kb];
        a[2] = *(const unsigned*)&As[(m0 + g)     * 136 + kb + 8];
        a[3] = *(const unsigned*)&As[(m0 + g + 8) * 136 + kb + 8];
        #pragma unroll
        for (int na = 0; na < 16; na++) {
            unsigned b[2];
            b[0] = *(const unsigned*)&Bt[(na * 8 + g) * 136 + kb];
            b[1] = *(const unsigned*)&Bt[(na * 8 + g) * 136 + kb + 8];
            mma16816(acc[na], a, b);
        }
    }
    __syncthreads();                 // done reading Bt; reuse it as C staging
    #pragma unroll
    for (int na = 0; na < 16; na++) {
        int cc = na * 8 + tg * 2;
        float2 bb = *(const float2*)&bl[c0 + cc];
        *(half2*)&Bt[(m0 + g) * 136 + cc]     = __floats2half2_rn(acc[na][0] + bb.x,
                                                                  acc[na][1] + bb.y);
        *(half2*)&Bt[(m0 + g + 8) * 136 + cc] = __floats2half2_rn(acc[na][2] + bb.x,
                                                                  acc[na][3] + bb.y);
    }
    __syncthreads();
    #pragma unroll
    for (int i = tid; i < 128 * 16; i += 256) {
        int r = i >> 4, c = i & 15;
        uint4 v = *(uint4*)&Bt[r * 136 + c * 8];
        *(uint4*)&g_gzh[(size_t)(bt0 + r) * 512 + c0 + c * 8] = v;
    }
}

// ---------------------------------------------------------------------------
// TENSOR LSTM v2: 16 blocks x 512 thr, 16 rows/block.
// Fix vs r5: gz staged through double-buffered smem via COALESCED loads
// (2x LDG.128/thread/step) instead of 8 scattered LDGs that flooded the
// L1tex wavefront queue and stalled the latency-critical ldmatrix path.
__global__ __launch_bounds__(512, 1) void k_lstm() {
    extern __shared__ char smc[];
    __half* hA  = (__half*)smc;                       // [16][136]
    __half* gzb = (__half*)(smc + 4352);              // [2][16][520]
    float*  zb  = (float*)(smc + 4352 + 66560 / 2 * 2);  // after gzb (66560 B)
    // layout: hA 4352 B | gzb 2*16*520*2 = 33280 B | zb 16*520*4 = 33280 B
    zb = (float*)(smc + 4352 + 33280);

    const int tid  = threadIdx.x;
    const int w    = tid >> 5, lane = tid & 31;
    const int g    = lane >> 2, tg = lane & 3;
    const int n0   = w * 32;
    const int b0   = blockIdx.x * 16;
    const int row  = w;                 // gate-stage batch row (0..15)

    // persistent B fragments: R^T[n0+nt*8+g][kt*16+tg*2 .. +1, +8..+9]
    unsigned wb[4][8][2];
    #pragma unroll
    for (int nt = 0; nt < 4; nt++)
        #pragma unroll
        for (int kt = 0; kt < 8; kt++) {
            const __half* rp = g_RTh + (size_t)(n0 + nt * 8 + g) * 128 + kt * 16 + tg * 2;
            wb[nt][kt][0] = *(const unsigned*)rp;
            wb[nt][kt][1] = *(const unsigned*)(rp + 8);
        }

    // zero h buffer
    for (int i = tid; i < 16 * 136 / 2; i += 512) ((unsigned*)hA)[i] = 0;
    float cst[4] = {0.f, 0.f, 0.f, 0.f};

    // chunk mapping for coalesced gz staging: chunk c (0..1023) -> row c>>6,
    // col (c&63)*8. Thread handles chunks tid and tid+512.
    const int r0c = tid >> 6,          cc0 = (tid & 63) * 8;
    const int r1c = (tid + 512) >> 6,  cc1 = ((tid + 512) & 63) * 8;
    const size_t gz_r0 = (size_t)(b0 + r0c) * T_ * 512 + cc0;
    const size_t gz_r1 = (size_t)(b0 + r1c) * T_ * 512 + cc1;

    // preload gz for t=0 into buffer 0
    *(uint4*)&gzb[r0c * 520 + cc0] = *(const uint4*)&g_gzh[gz_r0];
    *(uint4*)&gzb[r1c * 520 + cc1] = *(const uint4*)&g_gzh[gz_r1];

    unsigned hA_s = (unsigned)__cvta_generic_to_shared(hA);
    const unsigned lds_off =
        ((unsigned)(((lane & 7) + ((lane >> 3) & 1) * 8) * 136 + (lane >> 4) * 8)) * 2;
    __syncthreads();

    int pp = 0;
    for (int t = 0; t < T_; t++) {
        // 1. issue coalesced prefetch LDGs for t+1 (consumed next step)
        uint4 pf0, pf1;
        const bool hasn = (t + 1 < T_);
        if (hasn) {
            pf0 = *(const uint4*)&g_gzh[gz_r0 + (size_t)(t + 1) * 512];
            pf1 = *(const uint4*)&g_gzh[gz_r1 + (size_t)(t + 1) * 512];
        }

        // 2. recurrent GEMM: z[16,512] = h @ R^T
        float zc[4][4];
        #pragma unroll
        for (int nt = 0; nt < 4; nt++)
            #pragma unroll
            for (int j = 0; j < 4; j++) zc[nt][j] = 0.f;

        #pragma unroll
        for (int kt = 0; kt < 8; kt++) {
            unsigned a[4];
            ldsm4(a, hA_s + lds_off + kt * 32);   // +kt*16 halves
            #pragma unroll
            for (int nt = 0; nt < 4; nt++) mma16816(zc[nt], a, wb[nt][kt]);
        }

        // 3. add gz (from smem stage) and write z exchange buffer
        const __half* gzp = gzb + pp * 8320;
        #pragma unroll
        for (int nt = 0; nt < 4; nt++) {
            int col = n0 + nt * 8 + tg * 2;
            float2 lo = __half22float2(*(const half2*)&gzp[g * 520 + col]);
            float2 hi = __half22float2(*(const half2*)&gzp[(g + 8) * 520 + col]);
            *(float2*)&zb[g * 520 + col]       = make_float2(zc[nt][0] + lo.x,
                                                             zc[nt][1] + lo.y);
            *(float2*)&zb[(g + 8) * 520 + col] = make_float2(zc[nt][2] + hi.x,
                                                             zc[nt][3] + hi.y);
        }
        __syncthreads();

        // 4. gate stage: warp w = batch row w, 4 units per lane
        #pragma unroll
        for (int j = 0; j < 4; j++) {
            int u = lane + 32 * j;
            float zi = zb[row * 520 + u];
            float zf = zb[row * 520 + 128 + u];
            float zg = zb[row * 520 + 256 + u];
            float zo = zb[row * 520 + 384 + u];
            cst[j] = sigt_(zf) * cst[j] + sigt_(zi) * tanha_(zg);
            float hv = sigt_(zo) * tanha_(cst[j]);
            hA[row * 136 + u] = __float2half(hv);
        }
        // 5. land prefetched gz into the alternate buffer
        if (hasn) {
            __half* gzn = gzb + (pp ^ 1) * 8320;
            *(uint4*)&gzn[r0c * 520 + cc0] = pf0;
            *(uint4*)&gzn[r1c * 520 + cc1] = pf1;
        }
        __syncthreads();

        // 6. flush h to gmem (read-read concurrent with next step's ldsm)
        {
            uint2 v = *(uint2*)&hA[row * 136 + lane * 4];
            *(uint2*)&g_hsh[((size_t)(b0 + row) * T_ + t) * 128 + lane * 4] = v;
        }
        pp ^= 1;
    }
}

// ---------------------------------------------------------------------------
// heads: [hs]@[Wrm|Wrs] via HMMA.  grid 1024, 256 thr.  tile 128x128, k=128.
__global__ __launch_bounds__(256) void k_heads(const float* __restrict__ brm,
                                               const float* __restrict__ brs) {
    extern __shared__ __half sm[];
    __half* As = sm;                 // [128][136]
    __half* Bt = sm + 128 * 136;     // [128][136]
    const int tid = threadIdx.x;
    const int bt0 = blockIdx.x * 128;

    const uint4* ap = (const uint4*)(g_hsh + (size_t)bt0 * 128);
    const uint4* bp = (const uint4*)g_WrTh;
    #pragma unroll
    for (int i = tid; i < 128 * 16; i += 256) {
        int r = i >> 4, c = i & 15;
        *(uint4*)&As[r * 136 + c * 8] = ap[r * 16 + c];
        *(uint4*)&Bt[r * 136 + c * 8] = bp[r * 16 + c];
    }
    __syncthreads();

    const int w = tid >> 5, l = tid & 31, g = l >> 2, tg = l & 3;
    const int m0 = w * 16;
    float acc[16][4];
    #pragma unroll
    for (int i = 0; i < 16; i++)
        #pragma unroll
        for (int j = 0; j < 4; j++) acc[i][j] = 0.f;

    #pragma unroll
    for (int kk = 0; kk < 8; kk++) {
        const int kb = kk * 16 + tg * 2;
        unsigned a[4];
        a[0] = *(const unsigned*)&As[(m0 + g)     * 136 + kb];
        a[1] = *(const unsigned*)&As[(m0 + g + 8) * 136 + kb];
        a[2] = *(const unsigned*)&As[(m0 + g)     * 136 + kb + 8];
        a[3] = *(const unsigned*)&As[(m0 + g + 8) * 136 + kb + 8];
        #pragma unroll
        for (int na = 0; na < 16; na++) {
            unsigned b[2];
            b[0] = *(const unsigned*)&Bt[(na * 8 + g) * 136 + kb];
            b[1] = *(const unsigned*)&Bt[(na * 8 + g) * 136 + kb + 8];
            mma16816(acc[na], a, b);
        }
    }
    #pragma unroll
    for (int na = 0; na < 16; na++) {
        int cc = na * 8 + tg * 2;                 // 0..127 within concat
        int r0 = bt0 + m0 + g, r1 = r0 + 8;
        if (cc < 64) {
            float2 bm = *(const float2*)&brm[cc];
            *(half2*)&g_pmh[(size_t)r0 * 64 + cc] =
                __floats2half2_rn(acc[na][0] + bm.x, acc[na][1] + bm.y);
            *(half2*)&g_pmh[(size_t)r1 * 64 + cc] =
                __floats2half2_rn(acc[na][2] + bm.x, acc[na][3] + bm.y);
        } else {
            int c2 = cc - 64;
            float2 bs = *(const float2*)&brs[c2];
            *(float2*)&g_ps[(size_t)r0 * 64 + c2] =
                make_float2(softplusf_(acc[na][0] + bs.x), softplusf_(acc[na][1] + bs.y));
            *(float2*)&g_ps[(size_t)r1 * 64 + c2] =
                make_float2(softplusf_(acc[na][2] + bs.x), softplusf_(acc[na][3] + bs.y));
        }
    }
}

// ---------------------------------------------------------------------------
// generator + recon term via HMMA, fused reduction.  grid 1024, 512 thr.
__global__ __launch_bounds__(512) void k_gen(const float* __restrict__ obs,
                                             const float* __restrict__ bgm,
                                             const float* __restrict__ bgs) {
    extern __shared__ __half sm[];
    __half* As = sm;                 // [128][72]
    __half* Bt = sm + 128 * 72;      // [256][72]
    __shared__ float red[16];
    const int tid = threadIdx.x;
    const int bt0 = blockIdx.x * 128;

    const uint4* ap = (const uint4*)(g_pmh + (size_t)bt0 * 64);
    #pragma unroll
    for (int i = tid; i < 128 * 8; i += 512) {
        int r = i >> 3, c = i & 7;
        *(uint4*)&As[r * 72 + c * 8] = ap[r * 8 + c];
    }
    const uint4* bp = (const uint4*)g_WgTh;
    #pragma unroll
    for (int i = tid; i < 256 * 8; i += 512) {
        int r = i >> 3, c = i & 7;
        *(uint4*)&Bt[r * 72 + c * 8] = bp[i];
    }
    __syncthreads();

    const int w = tid >> 5, l = tid & 31, g = l >> 2, tg = l & 3;
    const int strip = w >> 1, ch = w & 1;
    const int m0 = strip * 16;
    float am[8][4], as_[8][4];
    #pragma unroll
    for (int i = 0; i < 8; i++)
        #pragma unroll
        for (int j = 0; j < 4; j++) { am[i][j] = 0.f; as_[i][j] = 0.f; }

    #pragma unroll
    for (int kk = 0; kk < 4; kk++) {
        const int kb = kk * 16 + tg * 2;
        unsigned a[4];
        a[0] = *(const unsigned*)&As[(m0 + g)     * 72 + kb];
        a[1] = *(const unsigned*)&As[(m0 + g + 8) * 72 + kb];
        a[2] = *(const unsigned*)&As[(m0 + g)     * 72 + kb + 8];
        a[3] = *(const unsigned*)&As[(m0 + g + 8) * 72 + kb + 8];
        #pragma unroll
        for (int na = 0; na < 8; na++) {
            int nmu = ch * 64 + na * 8 + g;
            unsigned b[2], b2[2];
            b[0]  = *(const unsigned*)&Bt[nmu * 72 + kb];
            b[1]  = *(const unsigned*)&Bt[nmu * 72 + kb + 8];
            b2[0] = *(const unsigned*)&Bt[(nmu + 128) * 72 + kb];
            b2[1] = *(const unsigned*)&Bt[(nmu + 128) * 72 + kb + 8];
            mma16816(am[na], a, b);
            mma16816(as_[na], a, b2);
        }
    }

    float lsum = 0.f;
    #pragma unroll
    for (int na = 0; na < 8; na++) {
        int oc = ch * 64 + na * 8 + tg * 2;
        float2 bm2 = *(const float2*)&bgm[oc];
        float2 bs2 = *(const float2*)&bgs[oc];
        int r0 = bt0 + m0 + g, r1 = r0 + 8;
        float2 o0 = *(const float2*)&obs[(size_t)r0 * 128 + oc];
        float2 o1 = *(const float2*)&obs[(size_t)r1 * 128 + oc];
        float mu, sg, d;
        mu = am[na][0] + bm2.x; sg = softplusf_(as_[na][0] + bs2.x);
        d = __fdividef(o0.x - mu, sg); lsum += -0.5f * d * d - __logf(sg);
        mu = am[na][1] + bm2.y; sg = softplusf_(as_[na][1] + bs2.y);
        d = __fdividef(o0.y - mu, sg); lsum += -0.5f * d * d - __logf(sg);
        mu = am[na][2] + bm2.x; sg = softplusf_(as_[na][2] + bs2.x);
        d = __fdividef(o1.x - mu, sg); lsum += -0.5f * d * d - __logf(sg);
        mu = am[na][3] + bm2.y; sg = softplusf_(as_[na][3] + bs2.y);
        d = __fdividef(o1.y - mu, sg); lsum += -0.5f * d * d - __logf(sg);
    }
    lsum -= 32.f * 0.91893853320467274f;   // 32 elements x 0.5*log(2pi)

    #pragma unroll
    for (int off = 16; off; off >>= 1) lsum += __shfl_down_sync(0xffffffffu, lsum, off);
    if (l == 0) red[w] = lsum;
    __syncthreads();
    if (tid == 0) {
        float s = 0.f;
        #pragma unroll
        for (int i = 0; i < 16; i++) s += red[i];
        atomicAdd(&g_acc[1], (double)s);
    }
}

// ---------------------------------------------------------------------------
// Prior rollout + KL, chunk-parallel via Aug-powers checkpoints.
__global__ __launch_bounds__(64) void k_prior2(const float* __restrict__ im,
                                               const float* __restrict__ Wfm,
                                               const float* __restrict__ bfm,
                                               const float* __restrict__ Wfs,
                                               const float* __restrict__ bfs) {
    __shared__ float  m0s[64];
    __shared__ __half mh[2][80];
    __shared__ float  red[2];
    const int s = threadIdx.x;
    const int b = blockIdx.x >> 3, j = blockIdx.x & 7;

    half2 wm[32], ws[32];
    #pragma unroll
    for (int q = 0; q < 32; q++) {
        wm[q] = __floats2half2_rn(Wfm[(2 * q) * 64 + s], Wfm[(2 * q + 1) * 64 + s]);
        ws[q] = __floats2half2_rn(Wfs[(2 * q) * 64 + s], Wfs[(2 * q + 1) * 64 + s]);
    }
    m0s[s] = im[b * 64 + s];
    const float bmv = bfm[s], bsv = bfs[s];
    __syncthreads();

    float mv;
    if (j == 0) {
        mv = m0s[s];
    } else {
        const float* CP = &g_cp[j - 1][0][0];
        float acc = CP[64 * 65 + s];
        #pragma unroll 16
        for (int k = 0; k < 64; k++) acc += m0s[k] * CP[k * 65 + s];
        mv = acc;
    }
    mh[0][s] = __float2half(mv);
    __syncthreads();

    const int t0 = j * 64;
    const __half* pmp = g_pmh + ((size_t)b * T_ + t0) * 64 + s;
    const float*  psp = g_ps  + ((size_t)b * T_ + t0) * 64 + s;
    float pmv = __half2float(pmp[0]);
    float psv = psp[0];

    const half2 z2 = __float2half2_rn(0.f);
    float klsum = 0.f;
    int pp = 0;
    for (int i = 0; i < 64; i++) {
        float npm = 0.f, nps = 1.f;
        if (i + 1 < 64) {
            npm = __half2float(pmp[(size_t)(i + 1) * 64]);
            nps = psp[(size_t)(i + 1) * 64];
        }
        const uint4* m4 = (const uint4*)mh[pp];
        half2 am0 = z2, am1 = z2, as0 = z2, as1 = z2;
        {
            uint4 q0 = m4[0], q1 = m4[1], q2 = m4[2], q3 = m4[3];
            const half2* x0 = (const half2*)&q0; const half2* x1 = (const half2*)&q1;
            const half2* x2 = (const half2*)&q2; const half2* x3 = (const half2*)&q3;
            #pragma unroll
            for (int q = 0; q < 4; q++) {
                am0 = __hfma2(wm[q], x0[q], am0);      as0 = __hfma2(ws[q], x0[q], as0);
                am0 = __hfma2(wm[4 + q], x1[q], am0);  as0 = __hfma2(ws[4 + q], x1[q], as0);
                am0 = __hfma2(wm[8 + q], x2[q], am0);  as0 = __hfma2(ws[8 + q], x2[q], as0);
                am0 = __hfma2(wm[12 + q], x3[q], am0); as0 = __hfma2(ws[12 + q], x3[q], as0);
            }
        }
        {
            uint4 q4 = m4[4], q5 = m4[5], q6 = m4[6], q7 = m4[7];
            const half2* x4 = (const half2*)&q4; const half2* x5 = (const half2*)&q5;
            const half2* x6 = (const half2*)&q6; const half2* x7 = (const half2*)&q7;
            #pragma unroll
            for (int q = 0; q < 4; q++) {
                am1 = __hfma2(wm[16 + q], x4[q], am1); as1 = __hfma2(ws[16 + q], x4[q], as1);
                am1 = __hfma2(wm[20 + q], x5[q], am1); as1 = __hfma2(ws[20 + q], x5[q], as1);
                am1 = __hfma2(wm[24 + q], x6[q], am1); as1 = __hfma2(ws[24 + q], x6[q], as1);
                am1 = __hfma2(wm[28 + q], x7[q], am1); as1 = __hfma2(ws[28 + q], x7[q], as1);
            }
        }
        float2 vm = __half22float2(__hadd2(am0, am1));
        float2 vs = __half22float2(__hadd2(as0, as1));
        float amv = bmv + vm.x + vm.y;
        float asv = bsv + vs.x + vs.y;

        float sn = softplusf_(asv);
        float d  = pmv - amv;
        klsum += __logf(__fdividef(sn, psv))
               + __fdividef(psv * psv + d * d, 2.f * sn * sn) - 0.5f;

        mh[pp ^ 1][s] = __float2half(amv);
        __syncthreads();
        pp ^= 1;
        pmv = npm; psv = nps;
    }
    #pragma unroll
    for (int off = 16; off; off >>= 1) klsum += __shfl_down_sync(0xffffffffu, klsum, off);
    if ((s & 31) == 0) red[s >> 5] = klsum;
    __syncthreads();
    if (s == 0) atomicAdd(&g_acc[0], (double)(red[0] + red[1]));
}

// ---------------------------------------------------------------------------
__global__ void k_fin(float* out) {
    out[0] = (float)(g_acc[0] / (double)BT_ - g_acc[1] / (double)B_);
}

// ---------------------------------------------------------------------------
extern "C" void kernel_launch(void* const* d_in, const int* in_sizes, int n_in,
                              void* d_out, int out_size) {
    const float* obs = (const float*)d_in[0];
    const float* im  = (const float*)d_in[1];
    // d_in[2] = initial_scale (unused by the reference computation)
    const float* Wfm = (const float*)d_in[3];
    const float* bfm = (const float*)d_in[4];
    const float* Wfs = (const float*)d_in[5];
    const float* bfs = (const float*)d_in[6];
    const float* Wgm = (const float*)d_in[7];
    const float* bgm = (const float*)d_in[8];
    const float* Wgs = (const float*)d_in[9];
    const float* bgs = (const float*)d_in[10];
    const float* K   = (const float*)d_in[11];
    const float* R   = (const float*)d_in[12];
    const float* bl  = (const float*)d_in[13];
    const float* Wrm = (const float*)d_in[14];
    const float* brm = (const float*)d_in[15];
    const float* Wrs = (const float*)d_in[16];
    const float* brs = (const float*)d_in[17];
    float* out = (float*)d_out;

    const int GEMM_SM = 2 * 128 * 136 * 2;          // 69632
    const int GEN_SM  = (128 * 72 + 256 * 72) * 2;  // 55296
    const int LSTM_SM = 4352 + 33280 + 33280;       // 70912
    cudaFuncSetAttribute(k_xk,    cudaFuncAttributeMaxDynamicSharedMemorySize, GEMM_SM);
    cudaFuncSetAttribute(k_lstm,  cudaFuncAttributeMaxDynamicSharedMemorySize, LSTM_SM);
    cudaFuncSetAttribute(k_heads, cudaFuncAttributeMaxDynamicSharedMemorySize, GEMM_SM);
    cudaFuncSetAttribute(k_gen,   cudaFuncAttributeMaxDynamicSharedMemorySize, GEN_SM);

    k_zero<<<1, 32>>>();
    k_prep_w<<<128, 256>>>(K, R, Wrm, Wrs, Wgm, Wgs);
    k_powers<<<1, 256>>>(Wfm, bfm);
    k_xk<<<dim3(4, 1024), 256, GEMM_SM>>>(obs, bl);
    k_lstm<<<16, 512, LSTM_SM>>>();
    k_heads<<<1024, 256, GEMM_SM>>>(brm, brs);
    k_gen<<<1024, 512, GEN_SM>>>(obs, bgm, bgs);
    k_prior2<<<2048, 64>>>(im, Wfm, bfm, Wfs, bfs);
    k_fin<<<1, 1>>>(out);
}

// round 10
// speedup vs baseline: 1.1825x; 1.1825x over previous
#include <cuda_runtime.h>
#include <cuda_fp16.h>
#include <math.h>

#define B_  256
#define T_  512
#define S_  64
#define O_  128
#define H_  128
#define G4  512   // 4*H
#define BT_ ((size_t)B_ * T_)

// ---------------- scratch (device globals; no runtime allocation) ----------
__device__ __half g_gzh[BT_ * G4];         // 134 MB : obs@K + b (half)
__device__ __half g_hsh[BT_ * H_];         // 33.5 MB LSTM hidden (half)
__device__ __half g_pmh[BT_ * S_];         // 16.8 MB posterior mean (half)
__device__ float  g_ps [BT_ * S_];         // 33.5 MB posterior scale (fp32)
__device__ __half g_KTh [512 * 128];       // K^T  (n-major)
__device__ __half g_WrTh[128 * 128];       // [Wrm|Wrs]^T (n-major, n<64 mean)
__device__ __half g_WgTh[256 * 64];        // [Wgm|Wgs]^T (n-major, n<128 mean)
__device__ float  g_cp[7][65][65];         // Aug^(64j), j=1..7
__device__ double g_acc[2];                // [0]=KL sum, [1]=recon-logp sum

__device__ __forceinline__ float softplusf_(float x) {
    return fmaxf(x, 0.f) + __logf(1.f + __expf(-fabsf(x)));
}
__device__ __forceinline__ float tanha_(float x) {
    float y; asm("tanh.approx.f32 %0, %1;" : "=f"(y) : "f"(x)); return y;
}
__device__ __forceinline__ float sigt_(float x) {   // sigmoid via MUFU.TANH
    return fmaf(tanha_(0.5f * x), 0.5f, 0.5f);
}

__device__ __forceinline__ void mma16816(float* c, const unsigned* a, const unsigned* b) {
    asm volatile(
        "mma.sync.aligned.m16n8k16.row.col.f32.f16.f16.f32 "
        "{%0,%1,%2,%3}, {%4,%5,%6,%7}, {%8,%9}, {%0,%1,%2,%3};\n"
        : "+f"(c[0]), "+f"(c[1]), "+f"(c[2]), "+f"(c[3])
        : "r"(a[0]), "r"(a[1]), "r"(a[2]), "r"(a[3]), "r"(b[0]), "r"(b[1]));
}

// ---------------------------------------------------------------------------
__global__ void k_zero() { if (threadIdx.x < 2) g_acc[threadIdx.x] = 0.0; }

// weight transposes/concats -> half
__global__ void k_prep_w(const float* __restrict__ K,  const float* __restrict__ Wrm,
                         const float* __restrict__ Wrs, const float* __restrict__ Wgm,
                         const float* __restrict__ Wgs) {
    int stride = gridDim.x * blockDim.x;
    for (int i = blockIdx.x * blockDim.x + threadIdx.x; i < 98304; i += stride) {
        if (i < 65536) {
            int n = i >> 7, k = i & 127;
            g_KTh[i] = __float2half(K[k * 512 + n]);
        } else if (i < 81920) {
            int j = i - 65536; int n = j >> 7, k = j & 127;
            float v = (n < 64) ? Wrm[k * 64 + n] : Wrs[k * 64 + (n - 64)];
            g_WrTh[j] = __float2half(v);
        } else {
            int j = i - 81920; int n = j >> 6, k = j & 63;
            float v = (n < 128) ? Wgm[k * 128 + n] : Wgs[k * 128 + (n - 128)];
            g_WgTh[j] = __float2half(v);
        }
    }
}

// ---------------------------------------------------------------------------
// Aug = [[Wfm, 0],[bfm, 1]] (65x65, row-vector convention).
// FMA-efficient products: thread (r,q) accumulates 16(+1) cols via float4 B
// reads + scalar A broadcast.  dst != src always; sync between products.
#define PW_N  65
#define PW_LD 68   // float4-aligned row stride
__device__ __forceinline__ void pw_mul(float* __restrict__ D,
                                       const float* __restrict__ A,
                                       const float* __restrict__ Bm, int tid) {
    const int q = tid & 3;              // col quarter
    for (int r = tid >> 2; r < PW_N; r += 64) {
        float acc[17];
        #pragma unroll
        for (int j = 0; j < 17; j++) acc[j] = 0.f;
        for (int k = 0; k < PW_N; k++) {
            float a = A[r * PW_LD + k];
            const float* br = &Bm[k * PW_LD + q * 16];
            float4 b0 = *(const float4*)br;
            float4 b1 = *(const float4*)(br + 4);
            float4 b2 = *(const float4*)(br + 8);
            float4 b3 = *(const float4*)(br + 12);
            acc[0]  += a * b0.x; acc[1]  += a * b0.y; acc[2]  += a * b0.z; acc[3]  += a * b0.w;
            acc[4]  += a * b1.x; acc[5]  += a * b1.y; acc[6]  += a * b1.z; acc[7]  += a * b1.w;
            acc[8]  += a * b2.x; acc[9]  += a * b2.y; acc[10] += a * b2.z; acc[11] += a * b2.w;
            acc[12] += a * b3.x; acc[13] += a * b3.y; acc[14] += a * b3.z; acc[15] += a * b3.w;
            if (q == 3) acc[16] += a * Bm[k * PW_LD + 64];
        }
        #pragma unroll
        for (int j = 0; j < 16; j++) D[r * PW_LD + q * 16 + j] = acc[j];
        if (q == 3) D[r * PW_LD + 64] = acc[16];
    }
}

__global__ __launch_bounds__(256) void k_powers(const float* __restrict__ Wfm,
                                                const float* __restrict__ bfm) {
    extern __shared__ float pw[];
    float* bufA = pw;                        // A64 (after phase 1)
    float* bufB = pw + PW_N * PW_LD;
    float* bufC = pw + 2 * PW_N * PW_LD;
    const int tid = threadIdx.x;

    for (int i = tid; i < PW_N * PW_N; i += 256) {
        int r = i / PW_N, s = i % PW_N;
        float v;
        if (r < 64 && s < 64)       v = Wfm[r * 64 + s];
        else if (r == 64 && s < 64) v = bfm[s];
        else                        v = (r == 64 && s == 64) ? 1.f : 0.f;
        bufA[r * PW_LD + s] = v;
    }
    __syncthreads();

    // 6 squarings (ping-pong A<->B): ends in bufA
    float* s_ = bufA; float* d_ = bufB;
    #pragma unroll 1
    for (int d = 0; d < 6; d++) {
        pw_mul(d_, s_, s_, tid);
        __syncthreads();
        float* t = s_; s_ = d_; d_ = t;
    }
    // s_ == bufA holds Aug^64
    for (int i = tid; i < PW_N * PW_N; i += 256)
        g_cp[0][i / PW_N][i % PW_N] = s_[(i / PW_N) * PW_LD + i % PW_N];
    __syncthreads();

    // Cur = A64; for j=2..7: Cur <- Cur*A64 (ping-pong B<->C)
    float* cur = s_; float* nxt = bufC;
    #pragma unroll 1
    for (int j = 2; j <= 7; j++) {
        pw_mul(nxt, cur, s_, tid);
        __syncthreads();
        for (int i = tid; i < PW_N * PW_N; i += 256)
            g_cp[j - 1][i / PW_N][i % PW_N] = nxt[(i / PW_N) * PW_LD + i % PW_N];
        float* t = (cur == s_) ? bufB : cur;   // after first product, rotate B<->C
        cur = nxt; nxt = t;
        __syncthreads();
    }
}

// ---------------------------------------------------------------------------
// gz = obs @ K + b via HMMA, output half. grid 1024: A tile loaded ONCE,
// internal loop over the 4 column blocks (obs read 1x instead of 4x).
__global__ __launch_bounds__(256) void k_xk(const float* __restrict__ obs,
                                            const float* __restrict__ bl) {
    extern __shared__ __half sm[];
    __half* As = sm;                 // [128][136]
    __half* Bt = sm + 128 * 136;     // [128][136]  (K^T tile / C staging)
    const int tid = threadIdx.x;
    const int bt0 = blockIdx.x * 128;

    const float4* ap = (const float4*)(obs + (size_t)bt0 * 128);
    #pragma unroll
    for (int i = tid; i < 128 * 32; i += 256) {
        int r = i >> 5, c = i & 31;
        float4 v = ap[r * 32 + c];
        *(half2*)&As[r * 136 + c * 4]     = __floats2half2_rn(v.x, v.y);
        *(half2*)&As[r * 136 + c * 4 + 2] = __floats2half2_rn(v.z, v.w);
    }
    __syncthreads();

    const int w = tid >> 5, l = tid & 31, g = l >> 2, tg = l & 3;
    const int m0 = w * 16;

    #pragma unroll 1
    for (int cb = 0; cb < 4; cb++) {
        const int c0 = cb * 128;
        const uint4* bp = (const uint4*)(g_KTh + (size_t)c0 * 128);
        #pragma unroll
        for (int i = tid; i < 128 * 16; i += 256) {
            int r = i >> 4, c = i & 15;
            *(uint4*)&Bt[r * 136 + c * 8] = bp[r * 16 + c];
        }
        __syncthreads();

        float acc[16][4];
        #pragma unroll
        for (int i = 0; i < 16; i++)
            #pragma unroll
            for (int j = 0; j < 4; j++) acc[i][j] = 0.f;

        #pragma unroll
        for (int kk = 0; kk < 8; kk++) {
            const int kb = kk * 16 + tg * 2;
            unsigned a[4];
            a[0] = *(const unsigned*)&As[(m0 + g)     * 136 + kb];
            a[1] = *(const unsigned*)&As[(m0 + g + 8) * 136 + kb];
            a[2] = *(const unsigned*)&As[(m0 + g)     * 136 + kb + 8];
            a[3] = *(const unsigned*)&As[(m0 + g + 8) * 136 + kb + 8];
            #pragma unroll
            for (int na = 0; na < 16; na++) {
                unsigned b[2];
                b[0] = *(const unsigned*)&Bt[(na * 8 + g) * 136 + kb];
                b[1] = *(const unsigned*)&Bt[(na * 8 + g) * 136 + kb + 8];
                mma16816(acc[na], a, b);
            }
        }
        __syncthreads();                 // done reading Bt; reuse as C staging
        #pragma unroll
        for (int na = 0; na < 16; na++) {
            int cc = na * 8 + tg * 2;
            float2 bb = *(const float2*)&bl[c0 + cc];
            *(half2*)&Bt[(m0 + g) * 136 + cc]     =
                __floats2half2_rn(acc[na][0] + bb.x, acc[na][1] + bb.y);
            *(half2*)&Bt[(m0 + g + 8) * 136 + cc] =
                __floats2half2_rn(acc[na][2] + bb.x, acc[na][3] + bb.y);
        }
        __syncthreads();
        #pragma unroll
        for (int i = tid; i < 128 * 16; i += 256) {
            int r = i >> 4, c = i & 15;
            uint4 v = *(uint4*)&Bt[r * 136 + c * 8];
            *(uint4*)&g_gzh[(size_t)(bt0 + r) * 512 + c0 + c * 8] = v;
        }
        __syncthreads();                 // stores done before next Bt load
    }
}

// ---------------------------------------------------------------------------
// LSTM recurrence: 128 blocks x 512 thr, 2 batch rows/block (proven config).
__global__ __launch_bounds__(512, 1) void k_lstm(const float* __restrict__ R) {
    __shared__ __half hh[2 * 128];
    __shared__ float  zbuf[2 * 512];
    const int tid = threadIdx.x;
    const int b0  = blockIdx.x * 2;

    half2 wreg[64];
    #pragma unroll
    for (int j = 0; j < 64; j++)
        wreg[j] = __floats2half2_rn(R[(size_t)(2 * j) * 512 + tid],
                                    R[(size_t)(2 * j + 1) * 512 + tid]);
    if (tid < 256) hh[tid] = __float2half(0.f);

    const __half* gz0 = g_gzh + (size_t)b0 * T_ * 512 + tid;
    const __half* gz1 = gz0 + (size_t)T_ * 512;
    const int r_ = tid >> 7, k_ = tid & 127;
    __half* hout = g_hsh + (size_t)(b0 + r_) * T_ * 128 + k_;
    float cst = 0.f;

    float gv0 = __half2float(gz0[0]);
    float gv1 = __half2float(gz1[0]);
    __syncthreads();

    const half2 z2 = __float2half2_rn(0.f);
    for (int t = 0; t < T_; t++) {
        float ngv0 = 0.f, ngv1 = 0.f;
        if (t + 1 < T_) {
            ngv0 = __half2float(gz0[(size_t)(t + 1) * 512]);
            ngv1 = __half2float(gz1[(size_t)(t + 1) * 512]);
        }
        float fs0 = gv0, fs1 = gv1;
        #pragma unroll
        for (int r = 0; r < 2; r++) {
            const uint4* hq = (const uint4*)(hh + r * 128);
            half2 a0 = z2, a1 = z2, a2 = z2, a3 = z2;
            #pragma unroll
            for (int q = 0; q < 4; q++) {
                uint4 v0 = hq[q], v1 = hq[4 + q], v2 = hq[8 + q], v3 = hq[12 + q];
                const half2* x0 = (const half2*)&v0;
                const half2* x1 = (const half2*)&v1;
                const half2* x2 = (const half2*)&v2;
                const half2* x3 = (const half2*)&v3;
                #pragma unroll
                for (int j = 0; j < 4; j++) {
                    a0 = __hfma2(wreg[q * 4 + j],      x0[j], a0);
                    a1 = __hfma2(wreg[16 + q * 4 + j], x1[j], a1);
                    a2 = __hfma2(wreg[32 + q * 4 + j], x2[j], a2);
                    a3 = __hfma2(wreg[48 + q * 4 + j], x3[j], a3);
                }
            }
            half2 s2 = __hadd2(__hadd2(a0, a1), __hadd2(a2, a3));
            float2 v = __half22float2(s2);
            if (r == 0) fs0 += v.x + v.y; else fs1 += v.x + v.y;
        }
        zbuf[tid]       = fs0;
        zbuf[512 + tid] = fs1;
        __syncthreads();
        if (tid < 256) {
            const float* zb = zbuf + r_ * 512;
            float zi = zb[k_], zf = zb[128 + k_], zg = zb[256 + k_], zo = zb[384 + k_];
            cst = sigt_(zf) * cst + sigt_(zi) * tanha_(zg);
            float hv = sigt_(zo) * tanha_(cst);
            __half h16 = __float2half(hv);
            hh[r_ * 128 + k_] = h16;
            hout[(size_t)t * 128] = h16;
        }
        __syncthreads();
        gv0 = ngv0; gv1 = ngv1;
    }
}

// ---------------------------------------------------------------------------
// heads: [hs]@[Wrm|Wrs] via HMMA.  grid 1024, 256 thr.  tile 128x128, k=128.
__global__ __launch_bounds__(256) void k_heads(const float* __restrict__ brm,
                                               const float* __restrict__ brs) {
    extern __shared__ __half sm[];
    __half* As = sm;                 // [128][136]
    __half* Bt = sm + 128 * 136;     // [128][136]
    const int tid = threadIdx.x;
    const int bt0 = blockIdx.x * 128;

    const uint4* ap = (const uint4*)(g_hsh + (size_t)bt0 * 128);
    const uint4* bp = (const uint4*)g_WrTh;
    #pragma unroll
    for (int i = tid; i < 128 * 16; i += 256) {
        int r = i >> 4, c = i & 15;
        *(uint4*)&As[r * 136 + c * 8] = ap[r * 16 + c];
        *(uint4*)&Bt[r * 136 + c * 8] = bp[r * 16 + c];
    }
    __syncthreads();

    const int w = tid >> 5, l = tid & 31, g = l >> 2, tg = l & 3;
    const int m0 = w * 16;
    float acc[16][4];
    #pragma unroll
    for (int i = 0; i < 16; i++)
        #pragma unroll
        for (int j = 0; j < 4; j++) acc[i][j] = 0.f;

    #pragma unroll
    for (int kk = 0; kk < 8; kk++) {
        const int kb = kk * 16 + tg * 2;
        unsigned a[4];
        a[0] = *(const unsigned*)&As[(m0 + g)     * 136 + kb];
        a[1] = *(const unsigned*)&As[(m0 + g + 8) * 136 + kb];
        a[2] = *(const unsigned*)&As[(m0 + g)     * 136 + kb + 8];
        a[3] = *(const unsigned*)&As[(m0 + g + 8) * 136 + kb + 8];
        #pragma unroll
        for (int na = 0; na < 16; na++) {
            unsigned b[2];
            b[0] = *(const unsigned*)&Bt[(na * 8 + g) * 136 + kb];
            b[1] = *(const unsigned*)&Bt[(na * 8 + g) * 136 + kb + 8];
            mma16816(acc[na], a, b);
        }
    }
    #pragma unroll
    for (int na = 0; na < 16; na++) {
        int cc = na * 8 + tg * 2;
        int r0 = bt0 + m0 + g, r1 = r0 + 8;
        if (cc < 64) {
            float2 bm = *(const float2*)&brm[cc];
            *(half2*)&g_pmh[(size_t)r0 * 64 + cc] =
                __floats2half2_rn(acc[na][0] + bm.x, acc[na][1] + bm.y);
            *(half2*)&g_pmh[(size_t)r1 * 64 + cc] =
                __floats2half2_rn(acc[na][2] + bm.x, acc[na][3] + bm.y);
        } else {
            int c2 = cc - 64;
            float2 bs = *(const float2*)&brs[c2];
            *(float2*)&g_ps[(size_t)r0 * 64 + c2] =
                make_float2(softplusf_(acc[na][0] + bs.x), softplusf_(acc[na][1] + bs.y));
            *(float2*)&g_ps[(size_t)r1 * 64 + c2] =
                make_float2(softplusf_(acc[na][2] + bs.x), softplusf_(acc[na][3] + bs.y));
        }
    }
}

// ---------------------------------------------------------------------------
// generator + recon term via HMMA, fused reduction.  grid 1024, 512 thr.
__global__ __launch_bounds__(512) void k_gen(const float* __restrict__ obs,
                                             const float* __restrict__ bgm,
                                             const float* __restrict__ bgs) {
    extern __shared__ __half sm[];
    __half* As = sm;                 // [128][72]
    __half* Bt = sm + 128 * 72;      // [256][72]
    __shared__ float red[16];
    const int tid = threadIdx.x;
    const int bt0 = blockIdx.x * 128;

    const uint4* ap = (const uint4*)(g_pmh + (size_t)bt0 * 64);
    #pragma unroll
    for (int i = tid; i < 128 * 8; i += 512) {
        int r = i >> 3, c = i & 7;
        *(uint4*)&As[r * 72 + c * 8] = ap[r * 8 + c];
    }
    const uint4* bp = (const uint4*)g_WgTh;
    #pragma unroll
    for (int i = tid; i < 256 * 8; i += 512) {
        int r = i >> 3, c = i & 7;
        *(uint4*)&Bt[r * 72 + c * 8] = bp[i];
    }
    __syncthreads();

    const int w = tid >> 5, l = tid & 31, g = l >> 2, tg = l & 3;
    const int strip = w >> 1, ch = w & 1;
    const int m0 = strip * 16;
    float am[8][4], as_[8][4];
    #pragma unroll
    for (int i = 0; i < 8; i++)
        #pragma unroll
        for (int j = 0; j < 4; j++) { am[i][j] = 0.f; as_[i][j] = 0.f; }

    #pragma unroll
    for (int kk = 0; kk < 4; kk++) {
        const int kb = kk * 16 + tg * 2;
        unsigned a[4];
        a[0] = *(const unsigned*)&As[(m0 + g)     * 72 + kb];
        a[1] = *(const unsigned*)&As[(m0 + g + 8) * 72 + kb];
        a[2] = *(const unsigned*)&As[(m0 + g)     * 72 + kb + 8];
        a[3] = *(const unsigned*)&As[(m0 + g + 8) * 72 + kb + 8];
        #pragma unroll
        for (int na = 0; na < 8; na++) {
            int nmu = ch * 64 + na * 8 + g;
            unsigned b[2], b2[2];
            b[0]  = *(const unsigned*)&Bt[nmu * 72 + kb];
            b[1]  = *(const unsigned*)&Bt[nmu * 72 + kb + 8];
            b2[0] = *(const unsigned*)&Bt[(nmu + 128) * 72 + kb];
            b2[1] = *(const unsigned*)&Bt[(nmu + 128) * 72 + kb + 8];
            mma16816(am[na], a, b);
            mma16816(as_[na], a, b2);
        }
    }

    float lsum = 0.f;
    #pragma unroll
    for (int na = 0; na < 8; na++) {
        int oc = ch * 64 + na * 8 + tg * 2;
        float2 bm2 = *(const float2*)&bgm[oc];
        float2 bs2 = *(const float2*)&bgs[oc];
        int r0 = bt0 + m0 + g, r1 = r0 + 8;
        float2 o0 = *(const float2*)&obs[(size_t)r0 * 128 + oc];
        float2 o1 = *(const float2*)&obs[(size_t)r1 * 128 + oc];
        float mu, sg, d;
        mu = am[na][0] + bm2.x; sg = softplusf_(as_[na][0] + bs2.x);
        d = __fdividef(o0.x - mu, sg); lsum += -0.5f * d * d - __logf(sg);
        mu = am[na][1] + bm2.y; sg = softplusf_(as_[na][1] + bs2.y);
        d = __fdividef(o0.y - mu, sg); lsum += -0.5f * d * d - __logf(sg);
        mu = am[na][2] + bm2.x; sg = softplusf_(as_[na][2] + bs2.x);
        d = __fdividef(o1.x - mu, sg); lsum += -0.5f * d * d - __logf(sg);
        mu = am[na][3] + bm2.y; sg = softplusf_(as_[na][3] + bs2.y);
        d = __fdividef(o1.y - mu, sg); lsum += -0.5f * d * d - __logf(sg);
    }
    lsum -= 32.f * 0.91893853320467274f;

    #pragma unroll
    for (int off = 16; off; off >>= 1) lsum += __shfl_down_sync(0xffffffffu, lsum, off);
    if (l == 0) red[w] = lsum;
    __syncthreads();
    if (tid == 0) {
        float s = 0.f;
        #pragma unroll
        for (int i = 0; i < 16; i++) s += red[i];
        atomicAdd(&g_acc[1], (double)s);
    }
}

// ---------------------------------------------------------------------------
// Prior rollout + KL, chunk-parallel via Aug-powers checkpoints.
__global__ __launch_bounds__(64) void k_prior2(const float* __restrict__ im,
                                               const float* __restrict__ Wfm,
                                               const float* __restrict__ bfm,
                                               const float* __restrict__ Wfs,
                                               const float* __restrict__ bfs) {
    __shared__ float  m0s[64];
    __shared__ __half mh[2][80];
    __shared__ float  red[2];
    const int s = threadIdx.x;
    const int b = blockIdx.x >> 3, j = blockIdx.x & 7;

    half2 wm[32], ws[32];
    #pragma unroll
    for (int q = 0; q < 32; q++) {
        wm[q] = __floats2half2_rn(Wfm[(2 * q) * 64 + s], Wfm[(2 * q + 1) * 64 + s]);
        ws[q] = __floats2half2_rn(Wfs[(2 * q) * 64 + s], Wfs[(2 * q + 1) * 64 + s]);
    }
    m0s[s] = im[b * 64 + s];
    const float bmv = bfm[s], bsv = bfs[s];
    __syncthreads();

    float mv;
    if (j == 0) {
        mv = m0s[s];
    } else {
        const float* CP = &g_cp[j - 1][0][0];
        float acc = CP[64 * 65 + s];
        #pragma unroll 16
        for (int k = 0; k < 64; k++) acc += m0s[k] * CP[k * 65 + s];
        mv = acc;
    }
    mh[0][s] = __float2half(mv);
    __syncthreads();

    const int t0 = j * 64;
    const __half* pmp = g_pmh + ((size_t)b * T_ + t0) * 64 + s;
    const float*  psp = g_ps  + ((size_t)b * T_ + t0) * 64 + s;
    float pmv = __half2float(pmp[0]);
    float psv = psp[0];

    const half2 z2 = __float2half2_rn(0.f);
    float klsum = 0.f;
    int pp = 0;
    for (int i = 0; i < 64; i++) {
        float npm = 0.f, nps = 1.f;
        if (i + 1 < 64) {
            npm = __half2float(pmp[(size_t)(i + 1) * 64]);
            nps = psp[(size_t)(i + 1) * 64];
        }
        const uint4* m4 = (const uint4*)mh[pp];
        half2 am0 = z2, am1 = z2, as0 = z2, as1 = z2;
        {
            uint4 q0 = m4[0], q1 = m4[1], q2 = m4[2], q3 = m4[3];
            const half2* x0 = (const half2*)&q0; const half2* x1 = (const half2*)&q1;
            const half2* x2 = (const half2*)&q2; const half2* x3 = (const half2*)&q3;
            #pragma unroll
            for (int q = 0; q < 4; q++) {
                am0 = __hfma2(wm[q], x0[q], am0);      as0 = __hfma2(ws[q], x0[q], as0);
                am0 = __hfma2(wm[4 + q], x1[q], am0);  as0 = __hfma2(ws[4 + q], x1[q], as0);
                am0 = __hfma2(wm[8 + q], x2[q], am0);  as0 = __hfma2(ws[8 + q], x2[q], as0);
                am0 = __hfma2(wm[12 + q], x3[q], am0); as0 = __hfma2(ws[12 + q], x3[q], as0);
            }
        }
        {
            uint4 q4 = m4[4], q5 = m4[5], q6 = m4[6], q7 = m4[7];
            const half2* x4 = (const half2*)&q4; const half2* x5 = (const half2*)&q5;
            const half2* x6 = (const half2*)&q6; const half2* x7 = (const half2*)&q7;
            #pragma unroll
            for (int q = 0; q < 4; q++) {
                am1 = __hfma2(wm[16 + q], x4[q], am1); as1 = __hfma2(ws[16 + q], x4[q], as1);
                am1 = __hfma2(wm[20 + q], x5[q], am1); as1 = __hfma2(ws[20 + q], x5[q], as1);
                am1 = __hfma2(wm[24 + q], x6[q], am1); as1 = __hfma2(ws[24 + q], x6[q], as1);
                am1 = __hfma2(wm[28 + q], x7[q], am1); as1 = __hfma2(ws[28 + q], x7[q], as1);
            }
        }
        float2 vm = __half22float2(__hadd2(am0, am1));
        float2 vs = __half22float2(__hadd2(as0, as1));
        float amv = bmv + vm.x + vm.y;
        float asv = bsv + vs.x + vs.y;

        float sn = softplusf_(asv);
        float d  = pmv - amv;
        klsum += __logf(__fdividef(sn, psv))
               + __fdividef(psv * psv + d * d, 2.f * sn * sn) - 0.5f;

        mh[pp ^ 1][s] = __float2half(amv);
        __syncthreads();
        pp ^= 1;
        pmv = npm; psv = nps;
    }
    #pragma unroll
    for (int off = 16; off; off >>= 1) klsum += __shfl_down_sync(0xffffffffu, klsum, off);
    if ((s & 31) == 0) red[s >> 5] = klsum;
    __syncthreads();
    if (s == 0) atomicAdd(&g_acc[0], (double)(red[0] + red[1]));
}

// ---------------------------------------------------------------------------
__global__ void k_fin(float* out) {
    out[0] = (float)(g_acc[0] / (double)BT_ - g_acc[1] / (double)B_);
}

// ---------------------------------------------------------------------------
extern "C" void kernel_launch(void* const* d_in, const int* in_sizes, int n_in,
                              void* d_out, int out_size) {
    const float* obs = (const float*)d_in[0];
    const float* im  = (const float*)d_in[1];
    // d_in[2] = initial_scale (unused by the reference computation)
    const float* Wfm = (const float*)d_in[3];
    const float* bfm = (const float*)d_in[4];
    const float* Wfs = (const float*)d_in[5];
    const float* bfs = (const float*)d_in[6];
    const float* Wgm = (const float*)d_in[7];
    const float* bgm = (const float*)d_in[8];
    const float* Wgs = (const float*)d_in[9];
    const float* bgs = (const float*)d_in[10];
    const float* K   = (const float*)d_in[11];
    const float* R   = (const float*)d_in[12];
    const float* bl  = (const float*)d_in[13];
    const float* Wrm = (const float*)d_in[14];
    const float* brm = (const float*)d_in[15];
    const float* Wrs = (const float*)d_in[16];
    const float* brs = (const float*)d_in[17];
    float* out = (float*)d_out;

    const int GEMM_SM = 2 * 128 * 136 * 2;              // 69632
    const int GEN_SM  = (128 * 72 + 256 * 72) * 2;      // 55296
    const int PW_SM   = 3 * PW_N * PW_LD * 4;           // 53040
    cudaFuncSetAttribute(k_xk,     cudaFuncAttributeMaxDynamicSharedMemorySize, GEMM_SM);
    cudaFuncSetAttribute(k_heads,  cudaFuncAttributeMaxDynamicSharedMemorySize, GEMM_SM);
    cudaFuncSetAttribute(k_gen,    cudaFuncAttributeMaxDynamicSharedMemorySize, GEN_SM);
    cudaFuncSetAttribute(k_powers, cudaFuncAttributeMaxDynamicSharedMemorySize, PW_SM);

    k_zero<<<1, 32>>>();
    k_prep_w<<<128, 256>>>(K, Wrm, Wrs, Wgm, Wgs);
    k_powers<<<1, 256, PW_SM>>>(Wfm, bfm);
    k_xk<<<1024, 256, GEMM_SM>>>(obs, bl);
    k_lstm<<<128, 512>>>(R);
    k_heads<<<1024, 256, GEMM_SM>>>(brm, brs);
    k_gen<<<1024, 512, GEN_SM>>>(obs, bgm, bgs);
    k_prior2<<<2048, 64>>>(im, Wfm, bfm, Wfs, bfs);
    k_fin<<<1, 1>>>(out);
}

// round 12
// speedup vs baseline: 1.2346x; 1.0441x over previous
#include <cuda_runtime.h>
#include <cuda_fp16.h>
#include <math.h>

#define B_  256
#define T_  512
#define S_  64
#define O_  128
#define H_  128
#define G4  512   // 4*H
#define BT_ ((size_t)B_ * T_)

// ---------------- scratch (device globals; no runtime allocation) ----------
__device__ __half g_gzh[BT_ * G4];         // 134 MB : obs@K + b (half)
__device__ __half g_hsh[BT_ * H_];         // 33.5 MB LSTM hidden (half)
__device__ __half g_pmh[BT_ * S_];         // 16.8 MB posterior mean (half)
__device__ float  g_ps [BT_ * S_];         // 33.5 MB posterior scale (fp32)
__device__ __half g_KTh [512 * 128];       // K^T  (n-major)
__device__ __half g_WrTh[128 * 128];       // [Wrm|Wrs]^T (n-major, n<64 mean)
__device__ __half g_WgTh[256 * 64];        // [Wgm|Wgs]^T (n-major, n<128 mean)
__device__ float  g_cp[7][65][65];         // Aug^(64j), j=1..7
__device__ double g_acc[2];                // [0]=KL sum, [1]=recon-logp sum

__device__ __forceinline__ float softplusf_(float x) {
    return fmaxf(x, 0.f) + __logf(1.f + __expf(-fabsf(x)));
}
__device__ __forceinline__ float tanha_(float x) {
    float y; asm("tanh.approx.f32 %0, %1;" : "=f"(y) : "f"(x)); return y;
}
__device__ __forceinline__ float sigt_(float x) {   // sigmoid via MUFU.TANH
    return fmaf(tanha_(0.5f * x), 0.5f, 0.5f);
}

__device__ __forceinline__ void mma16816(float* c, const unsigned* a, const unsigned* b) {
    asm volatile(
        "mma.sync.aligned.m16n8k16.row.col.f32.f16.f16.f32 "
        "{%0,%1,%2,%3}, {%4,%5,%6,%7}, {%8,%9}, {%0,%1,%2,%3};\n"
        : "+f"(c[0]), "+f"(c[1]), "+f"(c[2]), "+f"(c[3])
        : "r"(a[0]), "r"(a[1]), "r"(a[2]), "r"(a[3]), "r"(b[0]), "r"(b[1]));
}

// ---------------------------------------------------------------------------
// Merged prep: block 0 = acc zero + Aug powers; blocks 1..128 = weight prep.
#define PW_N  65
#define PW_LD 68
__device__ __forceinline__ void pw_mul(float* __restrict__ D,
                                       const float* __restrict__ A,
                                       const float* __restrict__ Bm, int tid) {
    const int q = tid & 3;
    for (int r = tid >> 2; r < PW_N; r += 64) {
        float acc[17];
        #pragma unroll
        for (int j = 0; j < 17; j++) acc[j] = 0.f;
        for (int k = 0; k < PW_N; k++) {
            float a = A[r * PW_LD + k];
            const float* br = &Bm[k * PW_LD + q * 16];
            float4 b0 = *(const float4*)br;
            float4 b1 = *(const float4*)(br + 4);
            float4 b2 = *(const float4*)(br + 8);
            float4 b3 = *(const float4*)(br + 12);
            acc[0]  += a * b0.x; acc[1]  += a * b0.y; acc[2]  += a * b0.z; acc[3]  += a * b0.w;
            acc[4]  += a * b1.x; acc[5]  += a * b1.y; acc[6]  += a * b1.z; acc[7]  += a * b1.w;
            acc[8]  += a * b2.x; acc[9]  += a * b2.y; acc[10] += a * b2.z; acc[11] += a * b2.w;
            acc[12] += a * b3.x; acc[13] += a * b3.y; acc[14] += a * b3.z; acc[15] += a * b3.w;
            if (q == 3) acc[16] += a * Bm[k * PW_LD + 64];
        }
        #pragma unroll
        for (int j = 0; j < 16; j++) D[r * PW_LD + q * 16 + j] = acc[j];
        if (q == 3) D[r * PW_LD + 64] = acc[16];
    }
}

__global__ __launch_bounds__(256) void k_prep(
        const float* __restrict__ K,   const float* __restrict__ Wrm,
        const float* __restrict__ Wrs, const float* __restrict__ Wgm,
        const float* __restrict__ Wgs, const float* __restrict__ Wfm,
        const float* __restrict__ bfm) {
    const int tid = threadIdx.x;
    if (blockIdx.x == 0) {
        // ---- zero accumulators + Aug powers ----
        if (tid < 2) g_acc[tid] = 0.0;
        extern __shared__ float pw[];
        float* bufA = pw;
        float* bufB = pw + PW_N * PW_LD;
        float* bufC = pw + 2 * PW_N * PW_LD;
        for (int i = tid; i < PW_N * PW_N; i += 256) {
            int r = i / PW_N, s = i % PW_N;
            float v;
            if (r < 64 && s < 64)       v = Wfm[r * 64 + s];
            else if (r == 64 && s < 64) v = bfm[s];
            else                        v = (r == 64 && s == 64) ? 1.f : 0.f;
            bufA[r * PW_LD + s] = v;
        }
        __syncthreads();
        float* s_ = bufA; float* d_ = bufB;
        #pragma unroll 1
        for (int d = 0; d < 6; d++) {
            pw_mul(d_, s_, s_, tid);
            __syncthreads();
            float* t = s_; s_ = d_; d_ = t;
        }
        for (int i = tid; i < PW_N * PW_N; i += 256)
            g_cp[0][i / PW_N][i % PW_N] = s_[(i / PW_N) * PW_LD + i % PW_N];
        __syncthreads();
        float* cur = s_; float* nxt = bufC;
        #pragma unroll 1
        for (int j = 2; j <= 7; j++) {
            pw_mul(nxt, cur, s_, tid);
            __syncthreads();
            for (int i = tid; i < PW_N * PW_N; i += 256)
                g_cp[j - 1][i / PW_N][i % PW_N] = nxt[(i / PW_N) * PW_LD + i % PW_N];
            float* t = (cur == s_) ? bufB : cur;
            cur = nxt; nxt = t;
            __syncthreads();
        }
    } else {
        // ---- weight transposes/concats -> half ----
        int stride = (gridDim.x - 1) * 256;
        for (int i = (blockIdx.x - 1) * 256 + tid; i < 98304; i += stride) {
            if (i < 65536) {
                int n = i >> 7, k = i & 127;
                g_KTh[i] = __float2half(K[k * 512 + n]);
            } else if (i < 81920) {
                int j = i - 65536; int n = j >> 7, k = j & 127;
                float v = (n < 64) ? Wrm[k * 64 + n] : Wrs[k * 64 + (n - 64)];
                g_WrTh[j] = __float2half(v);
            } else {
                int j = i - 81920; int n = j >> 6, k = j & 63;
                float v = (n < 128) ? Wgm[k * 128 + n] : Wgs[k * 128 + (n - 128)];
                g_WgTh[j] = __float2half(v);
            }
        }
    }
}

// ---------------------------------------------------------------------------
// gz = obs @ K + b via HMMA (r7 version: grid (4,1024), best measured 87us).
__global__ __launch_bounds__(256) void k_xk(const float* __restrict__ obs,
                                            const float* __restrict__ bl) {
    extern __shared__ __half sm[];
    __half* As = sm;                 // [128][136]
    __half* Bt = sm + 128 * 136;     // [128][136]  (K^T tile / C staging)
    const int tid = threadIdx.x;
    const int bt0 = blockIdx.y * 128;
    const int c0  = blockIdx.x * 128;

    const float4* ap = (const float4*)(obs + (size_t)bt0 * 128);
    #pragma unroll
    for (int i = tid; i < 128 * 32; i += 256) {
        int r = i >> 5, c = i & 31;
        float4 v = ap[r * 32 + c];
        *(half2*)&As[r * 136 + c * 4]     = __floats2half2_rn(v.x, v.y);
        *(half2*)&As[r * 136 + c * 4 + 2] = __floats2half2_rn(v.z, v.w);
    }
    const uint4* bp = (const uint4*)(g_KTh + (size_t)c0 * 128);
    #pragma unroll
    for (int i = tid; i < 128 * 16; i += 256) {
        int r = i >> 4, c = i & 15;
        *(uint4*)&Bt[r * 136 + c * 8] = bp[r * 16 + c];
    }
    __syncthreads();

    const int w = tid >> 5, l = tid & 31, g = l >> 2, tg = l & 3;
    const int m0 = w * 16;
    float acc[16][4];
    #pragma unroll
    for (int i = 0; i < 16; i++)
        #pragma unroll
        for (int j = 0; j < 4; j++) acc[i][j] = 0.f;

    #pragma unroll
    for (int kk = 0; kk < 8; kk++) {
        const int kb = kk * 16 + tg * 2;
        unsigned a[4];
        a[0] = *(const unsigned*)&As[(m0 + g)     * 136 + kb];
        a[1] = *(const unsigned*)&As[(m0 + g + 8) * 136 + kb];
        a[2] = *(const unsigned*)&As[(m0 + g)     * 136 + kb + 8];
        a[3] = *(const unsigned*)&As[(m0 + g + 8) * 136 + kb + 8];
        #pragma unroll
        for (int na = 0; na < 16; na++) {
            unsigned b[2];
            b[0] = *(const unsigned*)&Bt[(na * 8 + g) * 136 + kb];
            b[1] = *(const unsigned*)&Bt[(na * 8 + g) * 136 + kb + 8];
            mma16816(acc[na], a, b);
        }
    }
    __syncthreads();                 // done reading Bt; reuse as C staging
    #pragma unroll
    for (int na = 0; na < 16; na++) {
        int cc = na * 8 + tg * 2;
        float2 bb = *(const float2*)&bl[c0 + cc];
        *(half2*)&Bt[(m0 + g) * 136 + cc]     = __floats2half2_rn(acc[na][0] + bb.x,
                                                                  acc[na][1] + bb.y);
        *(half2*)&Bt[(m0 + g + 8) * 136 + cc] = __floats2half2_rn(acc[na][2] + bb.x,
                                                                  acc[na][3] + bb.y);
    }
    __syncthreads();
    #pragma unroll
    for (int i = tid; i < 128 * 16; i += 256) {
        int r = i >> 4, c = i & 15;
        uint4 v = *(uint4*)&Bt[r * 136 + c * 8];
        *(uint4*)&g_gzh[(size_t)(bt0 + r) * 512 + c0 + c * 8] = v;
    }
}

// ---------------------------------------------------------------------------
// LSTM recurrence: 128 blocks x 512 thr, 2 batch rows/block (proven config).
__global__ __launch_bounds__(512, 1) void k_lstm(const float* __restrict__ R) {
    __shared__ __half hh[2 * 128];
    __shared__ float  zbuf[2 * 512];
    const int tid = threadIdx.x;
    const int b0  = blockIdx.x * 2;

    half2 wreg[64];
    #pragma unroll
    for (int j = 0; j < 64; j++)
        wreg[j] = __floats2half2_rn(R[(size_t)(2 * j) * 512 + tid],
                                    R[(size_t)(2 * j + 1) * 512 + tid]);
    if (tid < 256) hh[tid] = __float2half(0.f);

    const __half* gz0 = g_gzh + (size_t)b0 * T_ * 512 + tid;
    const __half* gz1 = gz0 + (size_t)T_ * 512;
    const int r_ = tid >> 7, k_ = tid & 127;
    __half* hout = g_hsh + (size_t)(b0 + r_) * T_ * 128 + k_;
    float cst = 0.f;

    float gv0 = __half2float(gz0[0]);
    float gv1 = __half2float(gz1[0]);
    __syncthreads();

    const half2 z2 = __float2half2_rn(0.f);
    for (int t = 0; t < T_; t++) {
        float ngv0 = 0.f, ngv1 = 0.f;
        if (t + 1 < T_) {
            ngv0 = __half2float(gz0[(size_t)(t + 1) * 512]);
            ngv1 = __half2float(gz1[(size_t)(t + 1) * 512]);
        }
        float fs0 = gv0, fs1 = gv1;
        #pragma unroll
        for (int r = 0; r < 2; r++) {
            const uint4* hq = (const uint4*)(hh + r * 128);
            half2 a0 = z2, a1 = z2, a2 = z2, a3 = z2;
            #pragma unroll
            for (int q = 0; q < 4; q++) {
                uint4 v0 = hq[q], v1 = hq[4 + q], v2 = hq[8 + q], v3 = hq[12 + q];
                const half2* x0 = (const half2*)&v0;
                const half2* x1 = (const half2*)&v1;
                const half2* x2 = (const half2*)&v2;
                const half2* x3 = (const half2*)&v3;
                #pragma unroll
                for (int j = 0; j < 4; j++) {
                    a0 = __hfma2(wreg[q * 4 + j],      x0[j], a0);
                    a1 = __hfma2(wreg[16 + q * 4 + j], x1[j], a1);
                    a2 = __hfma2(wreg[32 + q * 4 + j], x2[j], a2);
                    a3 = __hfma2(wreg[48 + q * 4 + j], x3[j], a3);
                }
            }
            half2 s2 = __hadd2(__hadd2(a0, a1), __hadd2(a2, a3));
            float2 v = __half22float2(s2);
            if (r == 0) fs0 += v.x + v.y; else fs1 += v.x + v.y;
        }
        zbuf[tid]       = fs0;
        zbuf[512 + tid] = fs1;
        __syncthreads();
        if (tid < 256) {
            const float* zb = zbuf + r_ * 512;
            float zi = zb[k_], zf = zb[128 + k_], zg = zb[256 + k_], zo = zb[384 + k_];
            cst = sigt_(zf) * cst + sigt_(zi) * tanha_(zg);
            float hv = sigt_(zo) * tanha_(cst);
            __half h16 = __float2half(hv);
            hh[r_ * 128 + k_] = h16;
            hout[(size_t)t * 128] = h16;
        }
        __syncthreads();
        gv0 = ngv0; gv1 = ngv1;
    }
}

// ---------------------------------------------------------------------------
// FUSED heads+gen: grid 1024, 256 thr, 128 bt-rows/block.
// Phase A: pm/ps = hs @ [Wrm|Wrs] (HMMA).  Phase B: stage pm into smem.
// Phase C: obs_mean/scale = pm @ [Wgm|Wgs] (HMMA) + recon reduction.
__global__ __launch_bounds__(256) void k_headsgen(
        const float* __restrict__ brm, const float* __restrict__ brs,
        const float* __restrict__ obs, const float* __restrict__ bgm,
        const float* __restrict__ bgs) {
    extern __shared__ __half sm[];
    __half* As = sm;                 // phase A: [128][136] hs tile
    __half* Bt = sm + 128 * 136;     // phase A: [128][136] WrT
    __half* pmA = sm;                // phase C: [128][72] pm tile
    __half* WgT = sm + 128 * 72;     // phase C: [256][72]
    __shared__ float red[8];
    const int tid = threadIdx.x;
    const int bt0 = blockIdx.x * 128;

    // ---- Phase A: heads GEMM ----
    const uint4* ap = (const uint4*)(g_hsh + (size_t)bt0 * 128);
    const uint4* bp = (const uint4*)g_WrTh;
    #pragma unroll
    for (int i = tid; i < 128 * 16; i += 256) {
        int r = i >> 4, c = i & 15;
        *(uint4*)&As[r * 136 + c * 8] = ap[r * 16 + c];
        *(uint4*)&Bt[r * 136 + c * 8] = bp[r * 16 + c];
    }
    __syncthreads();

    const int w = tid >> 5, l = tid & 31, g = l >> 2, tg = l & 3;
    const int m0 = w * 16;
    {
        float acc[16][4];
        #pragma unroll
        for (int i = 0; i < 16; i++)
            #pragma unroll
            for (int j = 0; j < 4; j++) acc[i][j] = 0.f;

        #pragma unroll
        for (int kk = 0; kk < 8; kk++) {
            const int kb = kk * 16 + tg * 2;
            unsigned a[4];
            a[0] = *(const unsigned*)&As[(m0 + g)     * 136 + kb];
            a[1] = *(const unsigned*)&As[(m0 + g + 8) * 136 + kb];
            a[2] = *(const unsigned*)&As[(m0 + g)     * 136 + kb + 8];
            a[3] = *(const unsigned*)&As[(m0 + g + 8) * 136 + kb + 8];
            #pragma unroll
            for (int na = 0; na < 16; na++) {
                unsigned b[2];
                b[0] = *(const unsigned*)&Bt[(na * 8 + g) * 136 + kb];
                b[1] = *(const unsigned*)&Bt[(na * 8 + g) * 136 + kb + 8];
                mma16816(acc[na], a, b);
            }
        }
        __syncthreads();             // all As/Bt reads done; safe to overwrite

        // ---- Phase B: distribute pm (smem + gmem) and ps (gmem) ----
        #pragma unroll
        for (int na = 0; na < 16; na++) {
            int cc = na * 8 + tg * 2;
            int lr0 = m0 + g, lr1 = lr0 + 8;
            int r0 = bt0 + lr0, r1 = bt0 + lr1;
            if (cc < 64) {
                float2 bm = *(const float2*)&brm[cc];
                half2 p0 = __floats2half2_rn(acc[na][0] + bm.x, acc[na][1] + bm.y);
                half2 p1 = __floats2half2_rn(acc[na][2] + bm.x, acc[na][3] + bm.y);
                *(half2*)&pmA[lr0 * 72 + cc] = p0;
                *(half2*)&pmA[lr1 * 72 + cc] = p1;
                *(half2*)&g_pmh[(size_t)r0 * 64 + cc] = p0;
                *(half2*)&g_pmh[(size_t)r1 * 64 + cc] = p1;
            } else {
                int c2 = cc - 64;
                float2 bs = *(const float2*)&brs[c2];
                *(float2*)&g_ps[(size_t)r0 * 64 + c2] =
                    make_float2(softplusf_(acc[na][0] + bs.x), softplusf_(acc[na][1] + bs.y));
                *(float2*)&g_ps[(size_t)r1 * 64 + c2] =
                    make_float2(softplusf_(acc[na][2] + bs.x), softplusf_(acc[na][3] + bs.y));
            }
        }
    }
    // load WgT [256][64] -> smem [256][72]
    const uint4* gp = (const uint4*)g_WgTh;
    #pragma unroll
    for (int i = tid; i < 256 * 8; i += 256) {
        int r = i >> 3, c = i & 7;
        *(uint4*)&WgT[r * 72 + c * 8] = gp[i];
    }
    __syncthreads();

    // ---- Phase C: gen GEMM + recon ----
    float lsum = 0.f;
    #pragma unroll 1
    for (int ch = 0; ch < 2; ch++) {
        float am[8][4], as_[8][4];
        #pragma unroll
        for (int i = 0; i < 8; i++)
            #pragma unroll
            for (int j = 0; j < 4; j++) { am[i][j] = 0.f; as_[i][j] = 0.f; }

        #pragma unroll
        for (int kk = 0; kk < 4; kk++) {
            const int kb = kk * 16 + tg * 2;
            unsigned a[4];
            a[0] = *(const unsigned*)&pmA[(m0 + g)     * 72 + kb];
            a[1] = *(const unsigned*)&pmA[(m0 + g + 8) * 72 + kb];
            a[2] = *(const unsigned*)&pmA[(m0 + g)     * 72 + kb + 8];
            a[3] = *(const unsigned*)&pmA[(m0 + g + 8) * 72 + kb + 8];
            #pragma unroll
            for (int na = 0; na < 8; na++) {
                int nmu = ch * 64 + na * 8 + g;
                unsigned b[2], b2[2];
                b[0]  = *(const unsigned*)&WgT[nmu * 72 + kb];
                b[1]  = *(const unsigned*)&WgT[nmu * 72 + kb + 8];
                b2[0] = *(const unsigned*)&WgT[(nmu + 128) * 72 + kb];
                b2[1] = *(const unsigned*)&WgT[(nmu + 128) * 72 + kb + 8];
                mma16816(am[na], a, b);
                mma16816(as_[na], a, b2);
            }
        }
        #pragma unroll
        for (int na = 0; na < 8; na++) {
            int oc = ch * 64 + na * 8 + tg * 2;
            float2 bm2 = *(const float2*)&bgm[oc];
            float2 bs2 = *(const float2*)&bgs[oc];
            int r0 = bt0 + m0 + g, r1 = r0 + 8;
            float2 o0 = *(const float2*)&obs[(size_t)r0 * 128 + oc];
            float2 o1 = *(const float2*)&obs[(size_t)r1 * 128 + oc];
            float mu, sg, d;
            mu = am[na][0] + bm2.x; sg = softplusf_(as_[na][0] + bs2.x);
            d = __fdividef(o0.x - mu, sg); lsum += -0.5f * d * d - __logf(sg);
            mu = am[na][1] + bm2.y; sg = softplusf_(as_[na][1] + bs2.y);
            d = __fdividef(o0.y - mu, sg); lsum += -0.5f * d * d - __logf(sg);
            mu = am[na][2] + bm2.x; sg = softplusf_(as_[na][2] + bs2.x);
            d = __fdividef(o1.x - mu, sg); lsum += -0.5f * d * d - __logf(sg);
            mu = am[na][3] + bm2.y; sg = softplusf_(as_[na][3] + bs2.y);
            d = __fdividef(o1.y - mu, sg); lsum += -0.5f * d * d - __logf(sg);
        }
    }
    lsum -= 64.f * 0.91893853320467274f;   // 64 elements x 0.5*log(2pi)

    #pragma unroll
    for (int off = 16; off; off >>= 1) lsum += __shfl_down_sync(0xffffffffu, lsum, off);
    if (l == 0) red[w] = lsum;
    __syncthreads();
    if (tid == 0) {
        float s = 0.f;
        #pragma unroll
        for (int i = 0; i < 8; i++) s += red[i];
        atomicAdd(&g_acc[1], (double)s);
    }
}

// ---------------------------------------------------------------------------
// Prior rollout + KL, chunk-parallel via Aug-powers checkpoints.
__global__ __launch_bounds__(64) void k_prior2(const float* __restrict__ im,
                                               const float* __restrict__ Wfm,
                                               const float* __restrict__ bfm,
                                               const float* __restrict__ Wfs,
                                               const float* __restrict__ bfs) {
    __shared__ float  m0s[64];
    __shared__ __half mh[2][80];
    __shared__ float  red[2];
    const int s = threadIdx.x;
    const int b = blockIdx.x >> 3, j = blockIdx.x & 7;

    half2 wm[32], ws[32];
    #pragma unroll
    for (int q = 0; q < 32; q++) {
        wm[q] = __floats2half2_rn(Wfm[(2 * q) * 64 + s], Wfm[(2 * q + 1) * 64 + s]);
        ws[q] = __floats2half2_rn(Wfs[(2 * q) * 64 + s], Wfs[(2 * q + 1) * 64 + s]);
    }
    m0s[s] = im[b * 64 + s];
    const float bmv = bfm[s], bsv = bfs[s];
    __syncthreads();

    float mv;
    if (j == 0) {
        mv = m0s[s];
    } else {
        const float* CP = &g_cp[j - 1][0][0];
        float acc = CP[64 * 65 + s];
        #pragma unroll 16
        for (int k = 0; k < 64; k++) acc += m0s[k] * CP[k * 65 + s];
        mv = acc;
    }
    mh[0][s] = __float2half(mv);
    __syncthreads();

    const int t0 = j * 64;
    const __half* pmp = g_pmh + ((size_t)b * T_ + t0) * 64 + s;
    const float*  psp = g_ps  + ((size_t)b * T_ + t0) * 64 + s;
    float pmv = __half2float(pmp[0]);
    float psv = psp[0];

    const half2 z2 = __float2half2_rn(0.f);
    float klsum = 0.f;
    int pp = 0;
    for (int i = 0; i < 64; i++) {
        float npm = 0.f, nps = 1.f;
        if (i + 1 < 64) {
            npm = __half2float(pmp[(size_t)(i + 1) * 64]);
            nps = psp[(size_t)(i + 1) * 64];
        }
        const uint4* m4 = (const uint4*)mh[pp];
        half2 am0 = z2, am1 = z2, as0 = z2, as1 = z2;
        {
            uint4 q0 = m4[0], q1 = m4[1], q2 = m4[2], q3 = m4[3];
            const half2* x0 = (const half2*)&q0; const half2* x1 = (const half2*)&q1;
            const half2* x2 = (const half2*)&q2; const half2* x3 = (const half2*)&q3;
            #pragma unroll
            for (int q = 0; q < 4; q++) {
                am0 = __hfma2(wm[q], x0[q], am0);      as0 = __hfma2(ws[q], x0[q], as0);
                am0 = __hfma2(wm[4 + q], x1[q], am0);  as0 = __hfma2(ws[4 + q], x1[q], as0);
                am0 = __hfma2(wm[8 + q], x2[q], am0);  as0 = __hfma2(ws[8 + q], x2[q], as0);
                am0 = __hfma2(wm[12 + q], x3[q], am0); as0 = __hfma2(ws[12 + q], x3[q], as0);
            }
        }
        {
            uint4 q4 = m4[4], q5 = m4[5], q6 = m4[6], q7 = m4[7];
            const half2* x4 = (const half2*)&q4; const half2* x5 = (const half2*)&q5;
            const half2* x6 = (const half2*)&q6; const half2* x7 = (const half2*)&q7;
            #pragma unroll
            for (int q = 0; q < 4; q++) {
                am1 = __hfma2(wm[16 + q], x4[q], am1); as1 = __hfma2(ws[16 + q], x4[q], as1);
                am1 = __hfma2(wm[20 + q], x5[q], am1); as1 = __hfma2(ws[20 + q], x5[q], as1);
                am1 = __hfma2(wm[24 + q], x6[q], am1); as1 = __hfma2(ws[24 + q], x6[q], as1);
                am1 = __hfma2(wm[28 + q], x7[q], am1); as1 = __hfma2(ws[28 + q], x7[q], as1);
            }
        }
        float2 vm = __half22float2(__hadd2(am0, am1));
        float2 vs = __half22float2(__hadd2(as0, as1));
        float amv = bmv + vm.x + vm.y;
        float asv = bsv + vs.x + vs.y;

        float sn = softplusf_(asv);
        float d  = pmv - amv;
        klsum += __logf(__fdividef(sn, psv))
               + __fdividef(psv * psv + d * d, 2.f * sn * sn) - 0.5f;

        mh[pp ^ 1][s] = __float2half(amv);
        __syncthreads();
        pp ^= 1;
        pmv = npm; psv = nps;
    }
    #pragma unroll
    for (int off = 16; off; off >>= 1) klsum += __shfl_down_sync(0xffffffffu, klsum, off);
    if ((s & 31) == 0) red[s >> 5] = klsum;
    __syncthreads();
    if (s == 0) atomicAdd(&g_acc[0], (double)(red[0] + red[1]));
}

// ---------------------------------------------------------------------------
__global__ void k_fin(float* out) {
    out[0] = (float)(g_acc[0] / (double)BT_ - g_acc[1] / (double)B_);
}

// ---------------------------------------------------------------------------
extern "C" void kernel_launch(void* const* d_in, const int* in_sizes, int n_in,
                              void* d_out, int out_size) {
    const float* obs = (const float*)d_in[0];
    const float* im  = (const float*)d_in[1];
    // d_in[2] = initial_scale (unused by the reference computation)
    const float* Wfm = (const float*)d_in[3];
    const float* bfm = (const float*)d_in[4];
    const float* Wfs = (const float*)d_in[5];
    const float* bfs = (const float*)d_in[6];
    const float* Wgm = (const float*)d_in[7];
    const float* bgm = (const float*)d_in[8];
    const float* Wgs = (const float*)d_in[9];
    const float* bgs = (const float*)d_in[10];
    const float* K   = (const float*)d_in[11];
    const float* R   = (const float*)d_in[12];
    const float* bl  = (const float*)d_in[13];
    const float* Wrm = (const float*)d_in[14];
    const float* brm = (const float*)d_in[15];
    const float* Wrs = (const float*)d_in[16];
    const float* brs = (const float*)d_in[17];
    float* out = (float*)d_out;

    const int GEMM_SM = 2 * 128 * 136 * 2;              // 69632
    const int PW_SM   = 3 * PW_N * PW_LD * 4;           // 53040
    cudaFuncSetAttribute(k_xk,       cudaFuncAttributeMaxDynamicSharedMemorySize, GEMM_SM);
    cudaFuncSetAttribute(k_headsgen, cudaFuncAttributeMaxDynamicSharedMemorySize, GEMM_SM);
    cudaFuncSetAttribute(k_prep,     cudaFuncAttributeMaxDynamicSharedMemorySize, PW_SM);

    k_prep<<<129, 256, PW_SM>>>(K, Wrm, Wrs, Wgm, Wgs, Wfm, bfm);
    k_xk<<<dim3(4, 1024), 256, GEMM_SM>>>(obs, bl);
    k_lstm<<<128, 512>>>(R);
    k_headsgen<<<1024, 256, GEMM_SM>>>(brm, brs, obs, bgm, bgs);
    k_prior2<<<2048, 64>>>(im, Wfm, bfm, Wfs, bfs);
    k_fin<<<1, 1>>>(out);
}

// round 13
// speedup vs baseline: 1.2404x; 1.0047x over previous
#include <cuda_runtime.h>
#include <cuda_fp16.h>
#include <math.h>

#define B_  256
#define T_  512
#define S_  64
#define O_  128
#define H_  128
#define G4  512   // 4*H
#define BT_ ((size_t)B_ * T_)

// ---------------- scratch (device globals; no runtime allocation) ----------
__device__ __half g_gzh[BT_ * G4];         // 134 MB : obs@K + b (half)
__device__ __half g_hsh[BT_ * H_];         // 33.5 MB LSTM hidden (half)
__device__ __half g_prm[BT_ * S_];         // 16.8 MB prior mean (half)
__device__ __half g_prs[BT_ * S_];         // 16.8 MB prior scale (half)
__device__ __half g_KTh [512 * 128];       // K^T  (n-major)
__device__ __half g_WrTh[128 * 128];       // [Wrm|Wrs]^T (n-major, n<64 mean)
__device__ __half g_WgTh[256 * 64];        // [Wgm|Wgs]^T (n-major, n<128 mean)
__device__ float  g_cp[7][65][65];         // Aug^(64j), j=1..7
__device__ double g_acc[2];                // [0]=KL sum, [1]=recon-logp sum

__device__ __forceinline__ float softplusf_(float x) {
    return fmaxf(x, 0.f) + __logf(1.f + __expf(-fabsf(x)));
}
__device__ __forceinline__ float tanha_(float x) {
    float y; asm("tanh.approx.f32 %0, %1;" : "=f"(y) : "f"(x)); return y;
}
__device__ __forceinline__ float sigt_(float x) {   // sigmoid via MUFU.TANH
    return fmaf(tanha_(0.5f * x), 0.5f, 0.5f);
}

__device__ __forceinline__ void mma16816(float* c, const unsigned* a, const unsigned* b) {
    asm volatile(
        "mma.sync.aligned.m16n8k16.row.col.f32.f16.f16.f32 "
        "{%0,%1,%2,%3}, {%4,%5,%6,%7}, {%8,%9}, {%0,%1,%2,%3};\n"
        : "+f"(c[0]), "+f"(c[1]), "+f"(c[2]), "+f"(c[3])
        : "r"(a[0]), "r"(a[1]), "r"(a[2]), "r"(a[3]), "r"(b[0]), "r"(b[1]));
}

// ---------------------------------------------------------------------------
// Merged prep: block 0 = acc zero + Aug powers; blocks 1..128 = weight prep.
#define PW_N  65
#define PW_LD 68
__device__ __forceinline__ void pw_mul(float* __restrict__ D,
                                       const float* __restrict__ A,
                                       const float* __restrict__ Bm, int tid) {
    const int q = tid & 3;
    for (int r = tid >> 2; r < PW_N; r += 64) {
        float acc[17];
        #pragma unroll
        for (int j = 0; j < 17; j++) acc[j] = 0.f;
        for (int k = 0; k < PW_N; k++) {
            float a = A[r * PW_LD + k];
            const float* br = &Bm[k * PW_LD + q * 16];
            float4 b0 = *(const float4*)br;
            float4 b1 = *(const float4*)(br + 4);
            float4 b2 = *(const float4*)(br + 8);
            float4 b3 = *(const float4*)(br + 12);
            acc[0]  += a * b0.x; acc[1]  += a * b0.y; acc[2]  += a * b0.z; acc[3]  += a * b0.w;
            acc[4]  += a * b1.x; acc[5]  += a * b1.y; acc[6]  += a * b1.z; acc[7]  += a * b1.w;
            acc[8]  += a * b2.x; acc[9]  += a * b2.y; acc[10] += a * b2.z; acc[11] += a * b2.w;
            acc[12] += a * b3.x; acc[13] += a * b3.y; acc[14] += a * b3.z; acc[15] += a * b3.w;
            if (q == 3) acc[16] += a * Bm[k * PW_LD + 64];
        }
        #pragma unroll
        for (int j = 0; j < 16; j++) D[r * PW_LD + q * 16 + j] = acc[j];
        if (q == 3) D[r * PW_LD + 64] = acc[16];
    }
}

__global__ __launch_bounds__(256) void k_prep(
        const float* __restrict__ K,   const float* __restrict__ Wrm,
        const float* __restrict__ Wrs, const float* __restrict__ Wgm,
        const float* __restrict__ Wgs, const float* __restrict__ Wfm,
        const float* __restrict__ bfm) {
    const int tid = threadIdx.x;
    if (blockIdx.x == 0) {
        // ---- zero accumulators + Aug powers ----
        if (tid < 2) g_acc[tid] = 0.0;
        extern __shared__ float pw[];
        float* bufA = pw;
        float* bufB = pw + PW_N * PW_LD;
        float* bufC = pw + 2 * PW_N * PW_LD;
        for (int i = tid; i < PW_N * PW_N; i += 256) {
            int r = i / PW_N, s = i % PW_N;
            float v;
            if (r < 64 && s < 64)       v = Wfm[r * 64 + s];
            else if (r == 64 && s < 64) v = bfm[s];
            else                        v = (r == 64 && s == 64) ? 1.f : 0.f;
            bufA[r * PW_LD + s] = v;
        }
        __syncthreads();
        float* s_ = bufA; float* d_ = bufB;
        #pragma unroll 1
        for (int d = 0; d < 6; d++) {
            pw_mul(d_, s_, s_, tid);
            __syncthreads();
            float* t = s_; s_ = d_; d_ = t;
        }
        for (int i = tid; i < PW_N * PW_N; i += 256)
            g_cp[0][i / PW_N][i % PW_N] = s_[(i / PW_N) * PW_LD + i % PW_N];
        __syncthreads();
        float* cur = s_; float* nxt = bufC;
        #pragma unroll 1
        for (int j = 2; j <= 7; j++) {
            pw_mul(nxt, cur, s_, tid);
            __syncthreads();
            for (int i = tid; i < PW_N * PW_N; i += 256)
                g_cp[j - 1][i / PW_N][i % PW_N] = nxt[(i / PW_N) * PW_LD + i % PW_N];
            float* t = (cur == s_) ? bufB : cur;
            cur = nxt; nxt = t;
            __syncthreads();
        }
    } else {
        // ---- weight transposes/concats -> half ----
        int stride = (gridDim.x - 1) * 256;
        for (int i = (blockIdx.x - 1) * 256 + tid; i < 98304; i += stride) {
            if (i < 65536) {
                int n = i >> 7, k = i & 127;
                g_KTh[i] = __float2half(K[k * 512 + n]);
            } else if (i < 81920) {
                int j = i - 65536; int n = j >> 7, k = j & 127;
                float v = (n < 64) ? Wrm[k * 64 + n] : Wrs[k * 64 + (n - 64)];
                g_WrTh[j] = __float2half(v);
            } else {
                int j = i - 81920; int n = j >> 6, k = j & 63;
                float v = (n < 128) ? Wgm[k * 128 + n] : Wgs[k * 128 + (n - 128)];
                g_WgTh[j] = __float2half(v);
            }
        }
    }
}

// ---------------------------------------------------------------------------
// Prior rollout (WRITES prior mean/scale), chunk-parallel via Aug checkpoints.
__global__ __launch_bounds__(64) void k_prior_roll(const float* __restrict__ im,
                                                   const float* __restrict__ Wfm,
                                                   const float* __restrict__ bfm,
                                                   const float* __restrict__ Wfs,
                                                   const float* __restrict__ bfs) {
    __shared__ float  m0s[64];
    __shared__ __half mh[2][80];
    const int s = threadIdx.x;
    const int b = blockIdx.x >> 3, j = blockIdx.x & 7;

    half2 wm[32], ws[32];
    #pragma unroll
    for (int q = 0; q < 32; q++) {
        wm[q] = __floats2half2_rn(Wfm[(2 * q) * 64 + s], Wfm[(2 * q + 1) * 64 + s]);
        ws[q] = __floats2half2_rn(Wfs[(2 * q) * 64 + s], Wfs[(2 * q + 1) * 64 + s]);
    }
    m0s[s] = im[b * 64 + s];
    const float bmv = bfm[s], bsv = bfs[s];
    __syncthreads();

    float mv;
    if (j == 0) {
        mv = m0s[s];
    } else {
        const float* CP = &g_cp[j - 1][0][0];
        float acc = CP[64 * 65 + s];
        #pragma unroll 16
        for (int k = 0; k < 64; k++) acc += m0s[k] * CP[k * 65 + s];
        mv = acc;
    }
    mh[0][s] = __float2half(mv);
    __syncthreads();

    const int t0 = j * 64;
    __half* prmp = g_prm + ((size_t)b * T_ + t0) * 64 + s;
    __half* prsp = g_prs + ((size_t)b * T_ + t0) * 64 + s;

    const half2 z2 = __float2half2_rn(0.f);
    int pp = 0;
    for (int i = 0; i < 64; i++) {
        const uint4* m4 = (const uint4*)mh[pp];
        half2 am0 = z2, am1 = z2, as0 = z2, as1 = z2;
        {
            uint4 q0 = m4[0], q1 = m4[1], q2 = m4[2], q3 = m4[3];
            const half2* x0 = (const half2*)&q0; const half2* x1 = (const half2*)&q1;
            const half2* x2 = (const half2*)&q2; const half2* x3 = (const half2*)&q3;
            #pragma unroll
            for (int q = 0; q < 4; q++) {
                am0 = __hfma2(wm[q], x0[q], am0);      as0 = __hfma2(ws[q], x0[q], as0);
                am0 = __hfma2(wm[4 + q], x1[q], am0);  as0 = __hfma2(ws[4 + q], x1[q], as0);
                am0 = __hfma2(wm[8 + q], x2[q], am0);  as0 = __hfma2(ws[8 + q], x2[q], as0);
                am0 = __hfma2(wm[12 + q], x3[q], am0); as0 = __hfma2(ws[12 + q], x3[q], as0);
            }
        }
        {
            uint4 q4 = m4[4], q5 = m4[5], q6 = m4[6], q7 = m4[7];
            const half2* x4 = (const half2*)&q4; const half2* x5 = (const half2*)&q5;
            const half2* x6 = (const half2*)&q6; const half2* x7 = (const half2*)&q7;
            #pragma unroll
            for (int q = 0; q < 4; q++) {
                am1 = __hfma2(wm[16 + q], x4[q], am1); as1 = __hfma2(ws[16 + q], x4[q], as1);
                am1 = __hfma2(wm[20 + q], x5[q], am1); as1 = __hfma2(ws[20 + q], x5[q], as1);
                am1 = __hfma2(wm[24 + q], x6[q], am1); as1 = __hfma2(ws[24 + q], x6[q], as1);
                am1 = __hfma2(wm[28 + q], x7[q], am1); as1 = __hfma2(ws[28 + q], x7[q], as1);
            }
        }
        float2 vm = __half22float2(__hadd2(am0, am1));
        float2 vs = __half22float2(__hadd2(as0, as1));
        float amv = bmv + vm.x + vm.y;
        float asv = bsv + vs.x + vs.y;
        float sn  = softplusf_(asv);

        prmp[(size_t)i * 64] = __float2half(amv);
        prsp[(size_t)i * 64] = __float2half(sn);

        mh[pp ^ 1][s] = __float2half(amv);
        __syncthreads();
        pp ^= 1;
    }
}

// ---------------------------------------------------------------------------
// gz = obs @ K + b via HMMA (grid (4,1024), best measured 87us).
__global__ __launch_bounds__(256) void k_xk(const float* __restrict__ obs,
                                            const float* __restrict__ bl) {
    extern __shared__ __half sm[];
    __half* As = sm;                 // [128][136]
    __half* Bt = sm + 128 * 136;     // [128][136]  (K^T tile / C staging)
    const int tid = threadIdx.x;
    const int bt0 = blockIdx.y * 128;
    const int c0  = blockIdx.x * 128;

    const float4* ap = (const float4*)(obs + (size_t)bt0 * 128);
    #pragma unroll
    for (int i = tid; i < 128 * 32; i += 256) {
        int r = i >> 5, c = i & 31;
        float4 v = ap[r * 32 + c];
        *(half2*)&As[r * 136 + c * 4]     = __floats2half2_rn(v.x, v.y);
        *(half2*)&As[r * 136 + c * 4 + 2] = __floats2half2_rn(v.z, v.w);
    }
    const uint4* bp = (const uint4*)(g_KTh + (size_t)c0 * 128);
    #pragma unroll
    for (int i = tid; i < 128 * 16; i += 256) {
        int r = i >> 4, c = i & 15;
        *(uint4*)&Bt[r * 136 + c * 8] = bp[r * 16 + c];
    }
    __syncthreads();

    const int w = tid >> 5, l = tid & 31, g = l >> 2, tg = l & 3;
    const int m0 = w * 16;
    float acc[16][4];
    #pragma unroll
    for (int i = 0; i < 16; i++)
        #pragma unroll
        for (int j = 0; j < 4; j++) acc[i][j] = 0.f;

    #pragma unroll
    for (int kk = 0; kk < 8; kk++) {
        const int kb = kk * 16 + tg * 2;
        unsigned a[4];
        a[0] = *(const unsigned*)&As[(m0 + g)     * 136 + kb];
        a[1] = *(const unsigned*)&As[(m0 + g + 8) * 136 + kb];
        a[2] = *(const unsigned*)&As[(m0 + g)     * 136 + kb + 8];
        a[3] = *(const unsigned*)&As[(m0 + g + 8) * 136 + kb + 8];
        #pragma unroll
        for (int na = 0; na < 16; na++) {
            unsigned b[2];
            b[0] = *(const unsigned*)&Bt[(na * 8 + g) * 136 + kb];
            b[1] = *(const unsigned*)&Bt[(na * 8 + g) * 136 + kb + 8];
            mma16816(acc[na], a, b);
        }
    }
    __syncthreads();                 // done reading Bt; reuse as C staging
    #pragma unroll
    for (int na = 0; na < 16; na++) {
        int cc = na * 8 + tg * 2;
        float2 bb = *(const float2*)&bl[c0 + cc];
        *(half2*)&Bt[(m0 + g) * 136 + cc]     = __floats2half2_rn(acc[na][0] + bb.x,
                                                                  acc[na][1] + bb.y);
        *(half2*)&Bt[(m0 + g + 8) * 136 + cc] = __floats2half2_rn(acc[na][2] + bb.x,
                                                                  acc[na][3] + bb.y);
    }
    __syncthreads();
    #pragma unroll
    for (int i = tid; i < 128 * 16; i += 256) {
        int r = i >> 4, c = i & 15;
        uint4 v = *(uint4*)&Bt[r * 136 + c * 8];
        *(uint4*)&g_gzh[(size_t)(bt0 + r) * 512 + c0 + c * 8] = v;
    }
}

// ---------------------------------------------------------------------------
// LSTM recurrence: 128 blocks x 512 thr, 2 batch rows/block (proven config).
__global__ __launch_bounds__(512, 1) void k_lstm(const float* __restrict__ R) {
    __shared__ __half hh[2 * 128];
    __shared__ float  zbuf[2 * 512];
    const int tid = threadIdx.x;
    const int b0  = blockIdx.x * 2;

    half2 wreg[64];
    #pragma unroll
    for (int j = 0; j < 64; j++)
        wreg[j] = __floats2half2_rn(R[(size_t)(2 * j) * 512 + tid],
                                    R[(size_t)(2 * j + 1) * 512 + tid]);
    if (tid < 256) hh[tid] = __float2half(0.f);

    const __half* gz0 = g_gzh + (size_t)b0 * T_ * 512 + tid;
    const __half* gz1 = gz0 + (size_t)T_ * 512;
    const int r_ = tid >> 7, k_ = tid & 127;
    __half* hout = g_hsh + (size_t)(b0 + r_) * T_ * 128 + k_;
    float cst = 0.f;

    float gv0 = __half2float(gz0[0]);
    float gv1 = __half2float(gz1[0]);
    __syncthreads();

    const half2 z2 = __float2half2_rn(0.f);
    for (int t = 0; t < T_; t++) {
        float ngv0 = 0.f, ngv1 = 0.f;
        if (t + 1 < T_) {
            ngv0 = __half2float(gz0[(size_t)(t + 1) * 512]);
            ngv1 = __half2float(gz1[(size_t)(t + 1) * 512]);
        }
        float fs0 = gv0, fs1 = gv1;
        #pragma unroll
        for (int r = 0; r < 2; r++) {
            const uint4* hq = (const uint4*)(hh + r * 128);
            half2 a0 = z2, a1 = z2, a2 = z2, a3 = z2;
            #pragma unroll
            for (int q = 0; q < 4; q++) {
                uint4 v0 = hq[q], v1 = hq[4 + q], v2 = hq[8 + q], v3 = hq[12 + q];
                const half2* x0 = (const half2*)&v0;
                const half2* x1 = (const half2*)&v1;
                const half2* x2 = (const half2*)&v2;
                const half2* x3 = (const half2*)&v3;
                #pragma unroll
                for (int j = 0; j < 4; j++) {
                    a0 = __hfma2(wreg[q * 4 + j],      x0[j], a0);
                    a1 = __hfma2(wreg[16 + q * 4 + j], x1[j], a1);
                    a2 = __hfma2(wreg[32 + q * 4 + j], x2[j], a2);
                    a3 = __hfma2(wreg[48 + q * 4 + j], x3[j], a3);
                }
            }
            half2 s2 = __hadd2(__hadd2(a0, a1), __hadd2(a2, a3));
            float2 v = __half22float2(s2);
            if (r == 0) fs0 += v.x + v.y; else fs1 += v.x + v.y;
        }
        zbuf[tid]       = fs0;
        zbuf[512 + tid] = fs1;
        __syncthreads();
        if (tid < 256) {
            const float* zb = zbuf + r_ * 512;
            float zi = zb[k_], zf = zb[128 + k_], zg = zb[256 + k_], zo = zb[384 + k_];
            cst = sigt_(zf) * cst + sigt_(zi) * tanha_(zg);
            float hv = sigt_(zo) * tanha_(cst);
            __half h16 = __float2half(hv);
            hh[r_ * 128 + k_] = h16;
            hout[(size_t)t * 128] = h16;
        }
        __syncthreads();
        gv0 = ngv0; gv1 = ngv1;
    }
}

// ---------------------------------------------------------------------------
// FUSED heads+KL+gen: grid 1024, 256 thr, 128 bt-rows/block.
// Phase A: pm/ps = hs @ [Wrm|Wrs] (HMMA).
// Phase B: KL vs precomputed prior (g_prm/g_prs) in registers; stage pm smem.
// Phase C: obs_mean/scale = pm @ [Wgm|Wgs] (HMMA) + recon reduction.
__global__ __launch_bounds__(256) void k_headsgen(
        const float* __restrict__ brm, const float* __restrict__ brs,
        const float* __restrict__ obs, const float* __restrict__ bgm,
        const float* __restrict__ bgs) {
    extern __shared__ __half sm[];
    __half* As = sm;                 // phase A: [128][136] hs tile
    __half* Bt = sm + 128 * 136;     // phase A: [128][136] WrT
    __half* pmA = sm;                // phase C: [128][72] pm tile
    __half* WgT = sm + 128 * 72;     // phase C: [256][72]
    __shared__ float red[8];
    const int tid = threadIdx.x;
    const int bt0 = blockIdx.x * 128;

    // ---- Phase A: heads GEMM ----
    const uint4* ap = (const uint4*)(g_hsh + (size_t)bt0 * 128);
    const uint4* bp = (const uint4*)g_WrTh;
    #pragma unroll
    for (int i = tid; i < 128 * 16; i += 256) {
        int r = i >> 4, c = i & 15;
        *(uint4*)&As[r * 136 + c * 8] = ap[r * 16 + c];
        *(uint4*)&Bt[r * 136 + c * 8] = bp[r * 16 + c];
    }
    __syncthreads();

    const int w = tid >> 5, l = tid & 31, g = l >> 2, tg = l & 3;
    const int m0 = w * 16;
    {
        float acc[16][4];
        #pragma unroll
        for (int i = 0; i < 16; i++)
            #pragma unroll
            for (int j = 0; j < 4; j++) acc[i][j] = 0.f;

        #pragma unroll
        for (int kk = 0; kk < 8; kk++) {
            const int kb = kk * 16 + tg * 2;
            unsigned a[4];
            a[0] = *(const unsigned*)&As[(m0 + g)     * 136 + kb];
            a[1] = *(const unsigned*)&As[(m0 + g + 8) * 136 + kb];
            a[2] = *(const unsigned*)&As[(m0 + g)     * 136 + kb + 8];
            a[3] = *(const unsigned*)&As[(m0 + g + 8) * 136 + kb + 8];
            #pragma unroll
            for (int na = 0; na < 16; na++) {
                unsigned b[2];
                b[0] = *(const unsigned*)&Bt[(na * 8 + g) * 136 + kb];
                b[1] = *(const unsigned*)&Bt[(na * 8 + g) * 136 + kb + 8];
                mma16816(acc[na], a, b);
            }
        }
        __syncthreads();             // all As/Bt reads done; safe to overwrite

        // ---- Phase B: KL (elementwise, pm/ps both in this thread) + pm stage ----
        float klsum = 0.f;
        #pragma unroll
        for (int na = 0; na < 8; na++) {
            int s0 = na * 8 + tg * 2;
            int lr0 = m0 + g, lr1 = lr0 + 8;
            int r0 = bt0 + lr0, r1 = bt0 + lr1;
            float2 bm = *(const float2*)&brm[s0];
            float2 bs = *(const float2*)&brs[s0];
            float pm00 = acc[na][0] + bm.x, pm01 = acc[na][1] + bm.y;
            float pm10 = acc[na][2] + bm.x, pm11 = acc[na][3] + bm.y;
            float sp00 = softplusf_(acc[na + 8][0] + bs.x);
            float sp01 = softplusf_(acc[na + 8][1] + bs.y);
            float sp10 = softplusf_(acc[na + 8][2] + bs.x);
            float sp11 = softplusf_(acc[na + 8][3] + bs.y);
            *(half2*)&pmA[lr0 * 72 + s0] = __floats2half2_rn(pm00, pm01);
            *(half2*)&pmA[lr1 * 72 + s0] = __floats2half2_rn(pm10, pm11);
            float2 am0 = __half22float2(*(const half2*)&g_prm[(size_t)r0 * 64 + s0]);
            float2 am1 = __half22float2(*(const half2*)&g_prm[(size_t)r1 * 64 + s0]);
            float2 sn0 = __half22float2(*(const half2*)&g_prs[(size_t)r0 * 64 + s0]);
            float2 sn1 = __half22float2(*(const half2*)&g_prs[(size_t)r1 * 64 + s0]);
            float d;
            d = pm00 - am0.x;
            klsum += __logf(__fdividef(sn0.x, sp00))
                   + __fdividef(sp00 * sp00 + d * d, 2.f * sn0.x * sn0.x) - 0.5f;
            d = pm01 - am0.y;
            klsum += __logf(__fdividef(sn0.y, sp01))
                   + __fdividef(sp01 * sp01 + d * d, 2.f * sn0.y * sn0.y) - 0.5f;
            d = pm10 - am1.x;
            klsum += __logf(__fdividef(sn1.x, sp10))
                   + __fdividef(sp10 * sp10 + d * d, 2.f * sn1.x * sn1.x) - 0.5f;
            d = pm11 - am1.y;
            klsum += __logf(__fdividef(sn1.y, sp11))
                   + __fdividef(sp11 * sp11 + d * d, 2.f * sn1.y * sn1.y) - 0.5f;
        }
        #pragma unroll
        for (int off = 16; off; off >>= 1)
            klsum += __shfl_down_sync(0xffffffffu, klsum, off);
        if (l == 0) red[w] = klsum;
        __syncthreads();
        if (tid == 0) {
            float s = 0.f;
            #pragma unroll
            for (int i = 0; i < 8; i++) s += red[i];
            atomicAdd(&g_acc[0], (double)s);
        }
    }
    // load WgT [256][64] -> smem [256][72]
    const uint4* gp = (const uint4*)g_WgTh;
    #pragma unroll
    for (int i = tid; i < 256 * 8; i += 256) {
        int r = i >> 3, c = i & 7;
        *(uint4*)&WgT[r * 72 + c * 8] = gp[i];
    }
    __syncthreads();

    // ---- Phase C: gen GEMM + recon ----
    float lsum = 0.f;
    #pragma unroll 1
    for (int ch = 0; ch < 2; ch++) {
        float am[8][4], as_[8][4];
        #pragma unroll
        for (int i = 0; i < 8; i++)
            #pragma unroll
            for (int j = 0; j < 4; j++) { am[i][j] = 0.f; as_[i][j] = 0.f; }

        #pragma unroll
        for (int kk = 0; kk < 4; kk++) {
            const int kb = kk * 16 + tg * 2;
            unsigned a[4];
            a[0] = *(const unsigned*)&pmA[(m0 + g)     * 72 + kb];
            a[1] = *(const unsigned*)&pmA[(m0 + g + 8) * 72 + kb];
            a[2] = *(const unsigned*)&pmA[(m0 + g)     * 72 + kb + 8];
            a[3] = *(const unsigned*)&pmA[(m0 + g + 8) * 72 + kb + 8];
            #pragma unroll
            for (int na = 0; na < 8; na++) {
                int nmu = ch * 64 + na * 8 + g;
                unsigned b[2], b2[2];
                b[0]  = *(const unsigned*)&WgT[nmu * 72 + kb];
                b[1]  = *(const unsigned*)&WgT[nmu * 72 + kb + 8];
                b2[0] = *(const unsigned*)&WgT[(nmu + 128) * 72 + kb];
                b2[1] = *(const unsigned*)&WgT[(nmu + 128) * 72 + kb + 8];
                mma16816(am[na], a, b);
                mma16816(as_[na], a, b2);
            }
        }
        #pragma unroll
        for (int na = 0; na < 8; na++) {
            int oc = ch * 64 + na * 8 + tg * 2;
            float2 bm2 = *(const float2*)&bgm[oc];
            float2 bs2 = *(const float2*)&bgs[oc];
            int r0 = bt0 + m0 + g, r1 = r0 + 8;
            float2 o0 = *(const float2*)&obs[(size_t)r0 * 128 + oc];
            float2 o1 = *(const float2*)&obs[(size_t)r1 * 128 + oc];
            float mu, sg, d;
            mu = am[na][0] + bm2.x; sg = softplusf_(as_[na][0] + bs2.x);
            d = __fdividef(o0.x - mu, sg); lsum += -0.5f * d * d - __logf(sg);
            mu = am[na][1] + bm2.y; sg = softplusf_(as_[na][1] + bs2.y);
            d = __fdividef(o0.y - mu, sg); lsum += -0.5f * d * d - __logf(sg);
            mu = am[na][2] + bm2.x; sg = softplusf_(as_[na][2] + bs2.x);
            d = __fdividef(o1.x - mu, sg); lsum += -0.5f * d * d - __logf(sg);
            mu = am[na][3] + bm2.y; sg = softplusf_(as_[na][3] + bs2.y);
            d = __fdividef(o1.y - mu, sg); lsum += -0.5f * d * d - __logf(sg);
        }
    }
    lsum -= 64.f * 0.91893853320467274f;   // 64 elements x 0.5*log(2pi)

    #pragma unroll
    for (int off = 16; off; off >>= 1) lsum += __shfl_down_sync(0xffffffffu, lsum, off);
    if (l == 0) red[w] = lsum;
    __syncthreads();
    if (tid == 0) {
        float s = 0.f;
        #pragma unroll
        for (int i = 0; i < 8; i++) s += red[i];
        atomicAdd(&g_acc[1], (double)s);
    }
}

// ---------------------------------------------------------------------------
__global__ void k_fin(float* out) {
    out[0] = (float)(g_acc[0] / (double)BT_ - g_acc[1] / (double)B_);
}

// ---------------------------------------------------------------------------
extern "C" void kernel_launch(void* const* d_in, const int* in_sizes, int n_in,
                              void* d_out, int out_size) {
    const float* obs = (const float*)d_in[0];
    const float* im  = (const float*)d_in[1];
    // d_in[2] = initial_scale (unused by the reference computation)
    const float* Wfm = (const float*)d_in[3];
    const float* bfm = (const float*)d_in[4];
    const float* Wfs = (const float*)d_in[5];
    const float* bfs = (const float*)d_in[6];
    const float* Wgm = (const float*)d_in[7];
    const float* bgm = (const float*)d_in[8];
    const float* Wgs = (const float*)d_in[9];
    const float* bgs = (const float*)d_in[10];
    const float* K   = (const float*)d_in[11];
    const float* R   = (const float*)d_in[12];
    const float* bl  = (const float*)d_in[13];
    const float* Wrm = (const float*)d_in[14];
    const float* brm = (const float*)d_in[15];
    const float* Wrs = (const float*)d_in[16];
    const float* brs = (const float*)d_in[17];
    float* out = (float*)d_out;

    const int GEMM_SM = 2 * 128 * 136 * 2;              // 69632
    const int PW_SM   = 3 * PW_N * PW_LD * 4;           // 53040
    cudaFuncSetAttribute(k_xk,       cudaFuncAttributeMaxDynamicSharedMemorySize, GEMM_SM);
    cudaFuncSetAttribute(k_headsgen, cudaFuncAttributeMaxDynamicSharedMemorySize, GEMM_SM);
    cudaFuncSetAttribute(k_prep,     cudaFuncAttributeMaxDynamicSharedMemorySize, PW_SM);

    k_prep<<<129, 256, PW_SM>>>(K, Wrm, Wrs, Wgm, Wgs, Wfm, bfm);
    k_prior_roll<<<2048, 64>>>(im, Wfm, bfm, Wfs, bfs);
    k_xk<<<dim3(4, 1024), 256, GEMM_SM>>>(obs, bl);
    k_lstm<<<128, 512>>>(R);
    k_headsgen<<<1024, 256, GEMM_SM>>>(brm, brs, obs, bgm, bgs);
    k_fin<<<1, 1>>>(out);
}

// round 14
// speedup vs baseline: 1.3117x; 1.0575x over previous
#include <cuda_runtime.h>
#include <cuda_fp16.h>
#include <math.h>

#define B_  256
#define T_  512
#define S_  64
#define O_  128
#define H_  128
#define G4  512   // 4*H
#define BT_ ((size_t)B_ * T_)

// ---------------- scratch (device globals; no runtime allocation) ----------
__device__ __half g_gzh[BT_ * G4];         // 134 MB : obs@K + b (half)
__device__ __half g_hsh[BT_ * H_];         // 33.5 MB LSTM hidden (half)
__device__ __half g_prm[BT_ * S_];         // 16.8 MB prior mean (half)
__device__ __half g_prs[BT_ * S_];         // 16.8 MB prior scale (half)
__device__ __half g_KTh [512 * 128];       // K^T  (n-major)
__device__ __half g_WrTh[128 * 128];       // [Wrm|Wrs]^T (n-major, n<64 mean)
__device__ __half g_WgTh[256 * 64];        // [Wgm|Wgs]^T (n-major, n<128 mean)
__device__ float  g_cp[7][65][65];         // Aug^(64j), j=1..7
__device__ double g_acc[2];                // [0]=KL sum, [1]=recon-logp sum
__device__ unsigned g_done;                // headsgen completion counter

__device__ __forceinline__ float softplusf_(float x) {
    return fmaxf(x, 0.f) + __logf(1.f + __expf(-fabsf(x)));
}
__device__ __forceinline__ float tanha_(float x) {
    float y; asm("tanh.approx.f32 %0, %1;" : "=f"(y) : "f"(x)); return y;
}
__device__ __forceinline__ float sigt_(float x) {   // sigmoid via MUFU.TANH
    return fmaf(tanha_(0.5f * x), 0.5f, 0.5f);
}

__device__ __forceinline__ void mma16816(float* c, const unsigned* a, const unsigned* b) {
    asm volatile(
        "mma.sync.aligned.m16n8k16.row.col.f32.f16.f16.f32 "
        "{%0,%1,%2,%3}, {%4,%5,%6,%7}, {%8,%9}, {%0,%1,%2,%3};\n"
        : "+f"(c[0]), "+f"(c[1]), "+f"(c[2]), "+f"(c[3])
        : "r"(a[0]), "r"(a[1]), "r"(a[2]), "r"(a[3]), "r"(b[0]), "r"(b[1]));
}

// ---------------------------------------------------------------------------
// Merged prep: block 0 = acc zero + Aug powers; blocks 1..128 = weight prep.
#define PW_N  65
#define PW_LD 68
__device__ __forceinline__ void pw_mul(float* __restrict__ D,
                                       const float* __restrict__ A,
                                       const float* __restrict__ Bm, int tid) {
    const int q = tid & 3;
    for (int r = tid >> 2; r < PW_N; r += 64) {
        float acc[17];
        #pragma unroll
        for (int j = 0; j < 17; j++) acc[j] = 0.f;
        for (int k = 0; k < PW_N; k++) {
            float a = A[r * PW_LD + k];
            const float* br = &Bm[k * PW_LD + q * 16];
            float4 b0 = *(const float4*)br;
            float4 b1 = *(const float4*)(br + 4);
            float4 b2 = *(const float4*)(br + 8);
            float4 b3 = *(const float4*)(br + 12);
            acc[0]  += a * b0.x; acc[1]  += a * b0.y; acc[2]  += a * b0.z; acc[3]  += a * b0.w;
            acc[4]  += a * b1.x; acc[5]  += a * b1.y; acc[6]  += a * b1.z; acc[7]  += a * b1.w;
            acc[8]  += a * b2.x; acc[9]  += a * b2.y; acc[10] += a * b2.z; acc[11] += a * b2.w;
            acc[12] += a * b3.x; acc[13] += a * b3.y; acc[14] += a * b3.z; acc[15] += a * b3.w;
            if (q == 3) acc[16] += a * Bm[k * PW_LD + 64];
        }
        #pragma unroll
        for (int j = 0; j < 16; j++) D[r * PW_LD + q * 16 + j] = acc[j];
        if (q == 3) D[r * PW_LD + 64] = acc[16];
    }
}

__global__ __launch_bounds__(256) void k_prep(
        const float* __restrict__ K,   const float* __restrict__ Wrm,
        const float* __restrict__ Wrs, const float* __restrict__ Wgm,
        const float* __restrict__ Wgs, const float* __restrict__ Wfm,
        const float* __restrict__ bfm) {
    const int tid = threadIdx.x;
    if (blockIdx.x == 0) {
        // ---- zero accumulators + Aug powers ----
        if (tid < 2) g_acc[tid] = 0.0;
        if (tid == 2) g_done = 0u;
        extern __shared__ float pw[];
        float* bufA = pw;
        float* bufB = pw + PW_N * PW_LD;
        float* bufC = pw + 2 * PW_N * PW_LD;
        for (int i = tid; i < PW_N * PW_N; i += 256) {
            int r = i / PW_N, s = i % PW_N;
            float v;
            if (r < 64 && s < 64)       v = Wfm[r * 64 + s];
            else if (r == 64 && s < 64) v = bfm[s];
            else                        v = (r == 64 && s == 64) ? 1.f : 0.f;
            bufA[r * PW_LD + s] = v;
        }
        __syncthreads();
        float* s_ = bufA; float* d_ = bufB;
        #pragma unroll 1
        for (int d = 0; d < 6; d++) {
            pw_mul(d_, s_, s_, tid);
            __syncthreads();
            float* t = s_; s_ = d_; d_ = t;
        }
        for (int i = tid; i < PW_N * PW_N; i += 256)
            g_cp[0][i / PW_N][i % PW_N] = s_[(i / PW_N) * PW_LD + i % PW_N];
        __syncthreads();
        float* cur = s_; float* nxt = bufC;
        #pragma unroll 1
        for (int j = 2; j <= 7; j++) {
            pw_mul(nxt, cur, s_, tid);
            __syncthreads();
            for (int i = tid; i < PW_N * PW_N; i += 256)
                g_cp[j - 1][i / PW_N][i % PW_N] = nxt[(i / PW_N) * PW_LD + i % PW_N];
            float* t = (cur == s_) ? bufB : cur;
            cur = nxt; nxt = t;
            __syncthreads();
        }
    } else {
        // ---- weight transposes/concats -> half ----
        int stride = (gridDim.x - 1) * 256;
        for (int i = (blockIdx.x - 1) * 256 + tid; i < 98304; i += stride) {
            if (i < 65536) {
                int n = i >> 7, k = i & 127;
                g_KTh[i] = __float2half(K[k * 512 + n]);
            } else if (i < 81920) {
                int j = i - 65536; int n = j >> 7, k = j & 127;
                float v = (n < 64) ? Wrm[k * 64 + n] : Wrs[k * 64 + (n - 64)];
                g_WrTh[j] = __float2half(v);
            } else {
                int j = i - 81920; int n = j >> 6, k = j & 63;
                float v = (n < 128) ? Wgm[k * 128 + n] : Wgs[k * 128 + (n - 128)];
                g_WgTh[j] = __float2half(v);
            }
        }
    }
}

// ---------------------------------------------------------------------------
// gz = obs @ K + b via HMMA (grid (4,1024), best measured 87us).
__global__ __launch_bounds__(256) void k_xk(const float* __restrict__ obs,
                                            const float* __restrict__ bl) {
    extern __shared__ __half sm[];
    __half* As = sm;                 // [128][136]
    __half* Bt = sm + 128 * 136;     // [128][136]  (K^T tile / C staging)
    const int tid = threadIdx.x;
    const int bt0 = blockIdx.y * 128;
    const int c0  = blockIdx.x * 128;

    const float4* ap = (const float4*)(obs + (size_t)bt0 * 128);
    #pragma unroll
    for (int i = tid; i < 128 * 32; i += 256) {
        int r = i >> 5, c = i & 31;
        float4 v = ap[r * 32 + c];
        *(half2*)&As[r * 136 + c * 4]     = __floats2half2_rn(v.x, v.y);
        *(half2*)&As[r * 136 + c * 4 + 2] = __floats2half2_rn(v.z, v.w);
    }
    const uint4* bp = (const uint4*)(g_KTh + (size_t)c0 * 128);
    #pragma unroll
    for (int i = tid; i < 128 * 16; i += 256) {
        int r = i >> 4, c = i & 15;
        *(uint4*)&Bt[r * 136 + c * 8] = bp[r * 16 + c];
    }
    __syncthreads();

    const int w = tid >> 5, l = tid & 31, g = l >> 2, tg = l & 3;
    const int m0 = w * 16;
    float acc[16][4];
    #pragma unroll
    for (int i = 0; i < 16; i++)
        #pragma unroll
        for (int j = 0; j < 4; j++) acc[i][j] = 0.f;

    #pragma unroll
    for (int kk = 0; kk < 8; kk++) {
        const int kb = kk * 16 + tg * 2;
        unsigned a[4];
        a[0] = *(const unsigned*)&As[(m0 + g)     * 136 + kb];
        a[1] = *(const unsigned*)&As[(m0 + g + 8) * 136 + kb];
        a[2] = *(const unsigned*)&As[(m0 + g)     * 136 + kb + 8];
        a[3] = *(const unsigned*)&As[(m0 + g + 8) * 136 + kb + 8];
        #pragma unroll
        for (int na = 0; na < 16; na++) {
            unsigned b[2];
            b[0] = *(const unsigned*)&Bt[(na * 8 + g) * 136 + kb];
            b[1] = *(const unsigned*)&Bt[(na * 8 + g) * 136 + kb + 8];
            mma16816(acc[na], a, b);
        }
    }
    __syncthreads();                 // done reading Bt; reuse as C staging
    #pragma unroll
    for (int na = 0; na < 16; na++) {
        int cc = na * 8 + tg * 2;
        float2 bb = *(const float2*)&bl[c0 + cc];
        *(half2*)&Bt[(m0 + g) * 136 + cc]     = __floats2half2_rn(acc[na][0] + bb.x,
                                                                  acc[na][1] + bb.y);
        *(half2*)&Bt[(m0 + g + 8) * 136 + cc] = __floats2half2_rn(acc[na][2] + bb.x,
                                                                  acc[na][3] + bb.y);
    }
    __syncthreads();
    #pragma unroll
    for (int i = tid; i < 128 * 16; i += 256) {
        int r = i >> 4, c = i & 15;
        uint4 v = *(uint4*)&Bt[r * 136 + c * 8];
        *(uint4*)&g_gzh[(size_t)(bt0 + r) * 512 + c0 + c * 8] = v;
    }
}

// ---------------------------------------------------------------------------
// HETEROGENEOUS kernel, grid 148 x 512 thr:
//   blocks 0..127  : LSTM recurrence (2 batch rows/block, proven config)
//   blocks 128..147: prior rollout (2048 chunk-units, 8 sub-units/block,
//                    13 grid-stride passes) -> writes g_prm/g_prs.
// The prior work (~320us on 20 SMs) hides entirely under the LSTM (~490us).
__global__ __launch_bounds__(512, 1) void k_lstm(const float* __restrict__ R,
                                                 const float* __restrict__ im,
                                                 const float* __restrict__ Wfm,
                                                 const float* __restrict__ bfm,
                                                 const float* __restrict__ Wfs,
                                                 const float* __restrict__ bfs) {
    __shared__ __half hh[2 * 128];
    __shared__ float  zbuf[2 * 512];
    __shared__ float  pm0s[8][64];
    __shared__ __half pmh[8][2][80];
    const int tid = threadIdx.x;

    if (blockIdx.x < 128) {
        // ================= LSTM path =================
        const int b0 = blockIdx.x * 2;

        half2 wreg[64];
        #pragma unroll
        for (int j = 0; j < 64; j++)
            wreg[j] = __floats2half2_rn(R[(size_t)(2 * j) * 512 + tid],
                                        R[(size_t)(2 * j + 1) * 512 + tid]);
        if (tid < 256) hh[tid] = __float2half(0.f);

        const __half* gz0 = g_gzh + (size_t)b0 * T_ * 512 + tid;
        const __half* gz1 = gz0 + (size_t)T_ * 512;
        const int r_ = tid >> 7, k_ = tid & 127;
        __half* hout = g_hsh + (size_t)(b0 + r_) * T_ * 128 + k_;
        float cst = 0.f;

        float gv0 = __half2float(gz0[0]);
        float gv1 = __half2float(gz1[0]);
        __syncthreads();

        const half2 z2 = __float2half2_rn(0.f);
        for (int t = 0; t < T_; t++) {
            float ngv0 = 0.f, ngv1 = 0.f;
            if (t + 1 < T_) {
                ngv0 = __half2float(gz0[(size_t)(t + 1) * 512]);
                ngv1 = __half2float(gz1[(size_t)(t + 1) * 512]);
            }
            float fs0 = gv0, fs1 = gv1;
            #pragma unroll
            for (int r = 0; r < 2; r++) {
                const uint4* hq = (const uint4*)(hh + r * 128);
                half2 a0 = z2, a1 = z2, a2 = z2, a3 = z2;
                #pragma unroll
                for (int q = 0; q < 4; q++) {
                    uint4 v0 = hq[q], v1 = hq[4 + q], v2 = hq[8 + q], v3 = hq[12 + q];
                    const half2* x0 = (const half2*)&v0;
                    const half2* x1 = (const half2*)&v1;
                    const half2* x2 = (const half2*)&v2;
                    const half2* x3 = (const half2*)&v3;
                    #pragma unroll
                    for (int j = 0; j < 4; j++) {
                        a0 = __hfma2(wreg[q * 4 + j],      x0[j], a0);
                        a1 = __hfma2(wreg[16 + q * 4 + j], x1[j], a1);
                        a2 = __hfma2(wreg[32 + q * 4 + j], x2[j], a2);
                        a3 = __hfma2(wreg[48 + q * 4 + j], x3[j], a3);
                    }
                }
                half2 s2 = __hadd2(__hadd2(a0, a1), __hadd2(a2, a3));
                float2 v = __half22float2(s2);
                if (r == 0) fs0 += v.x + v.y; else fs1 += v.x + v.y;
            }
            zbuf[tid]       = fs0;
            zbuf[512 + tid] = fs1;
            __syncthreads();
            if (tid < 256) {
                const float* zb = zbuf + r_ * 512;
                float zi = zb[k_], zf = zb[128 + k_], zg = zb[256 + k_], zo = zb[384 + k_];
                cst = sigt_(zf) * cst + sigt_(zi) * tanha_(zg);
                float hv = sigt_(zo) * tanha_(cst);
                __half h16 = __float2half(hv);
                hh[r_ * 128 + k_] = h16;
                hout[(size_t)t * 128] = h16;
            }
            __syncthreads();
            gv0 = ngv0; gv1 = ngv1;
        }
    } else {
        // ================= Prior rollout path =================
        const int p  = blockIdx.x - 128;   // 0..19
        const int s  = tid & 63;           // state element
        const int su = tid >> 6;           // sub-unit 0..7

        half2 wm[32], ws[32];
        #pragma unroll
        for (int q = 0; q < 32; q++) {
            wm[q] = __floats2half2_rn(Wfm[(2 * q) * 64 + s], Wfm[(2 * q + 1) * 64 + s]);
            ws[q] = __floats2half2_rn(Wfs[(2 * q) * 64 + s], Wfs[(2 * q + 1) * 64 + s]);
        }
        const float bmv = bfm[s], bsv = bfs[s];
        const half2 z2 = __float2half2_rn(0.f);

        #pragma unroll 1
        for (int iter = 0; iter < 13; iter++) {      // ceil(2048/160)
            const int u = iter * 160 + p * 8 + su;   // chunk-unit id
            const bool valid = (u < 2048);
            const int b = u >> 3, j = u & 7;

            if (valid) pm0s[su][s] = im[b * 64 + s];
            __syncthreads();

            if (valid) {
                float mv;
                if (j == 0) {
                    mv = pm0s[su][s];
                } else {
                    const float* CP = &g_cp[j - 1][0][0];
                    float acc = CP[64 * 65 + s];
                    #pragma unroll 16
                    for (int k = 0; k < 64; k++) acc += pm0s[su][k] * CP[k * 65 + s];
                    mv = acc;
                }
                pmh[su][0][s] = __float2half(mv);
            }
            __syncthreads();

            const int t0 = j * 64;
            __half* prmp = g_prm + ((size_t)b * T_ + t0) * 64 + s;
            __half* prsp = g_prs + ((size_t)b * T_ + t0) * 64 + s;

            int pp = 0;
            #pragma unroll 1
            for (int i = 0; i < 64; i++) {
                if (valid) {
                    const uint4* m4 = (const uint4*)pmh[su][pp];
                    half2 am0 = z2, am1 = z2, as0 = z2, as1 = z2;
                    {
                        uint4 q0 = m4[0], q1 = m4[1], q2 = m4[2], q3 = m4[3];
                        const half2* x0 = (const half2*)&q0; const half2* x1 = (const half2*)&q1;
                        const half2* x2 = (const half2*)&q2; const half2* x3 = (const half2*)&q3;
                        #pragma unroll
                        for (int q = 0; q < 4; q++) {
                            am0 = __hfma2(wm[q], x0[q], am0);      as0 = __hfma2(ws[q], x0[q], as0);
                            am0 = __hfma2(wm[4 + q], x1[q], am0);  as0 = __hfma2(ws[4 + q], x1[q], as0);
                            am0 = __hfma2(wm[8 + q], x2[q], am0);  as0 = __hfma2(ws[8 + q], x2[q], as0);
                            am0 = __hfma2(wm[12 + q], x3[q], am0); as0 = __hfma2(ws[12 + q], x3[q], as0);
                        }
                    }
                    {
                        uint4 q4 = m4[4], q5 = m4[5], q6 = m4[6], q7 = m4[7];
                        const half2* x4 = (const half2*)&q4; const half2* x5 = (const half2*)&q5;
                        const half2* x6 = (const half2*)&q6; const half2* x7 = (const half2*)&q7;
                        #pragma unroll
                        for (int q = 0; q < 4; q++) {
                            am1 = __hfma2(wm[16 + q], x4[q], am1); as1 = __hfma2(ws[16 + q], x4[q], as1);
                            am1 = __hfma2(wm[20 + q], x5[q], am1); as1 = __hfma2(ws[20 + q], x5[q], as1);
                            am1 = __hfma2(wm[24 + q], x6[q], am1); as1 = __hfma2(ws[24 + q], x6[q], as1);
                            am1 = __hfma2(wm[28 + q], x7[q], am1); as1 = __hfma2(ws[28 + q], x7[q], as1);
                        }
                    }
                    float2 vm = __half22float2(__hadd2(am0, am1));
                    float2 vs = __half22float2(__hadd2(as0, as1));
                    float amv = bmv + vm.x + vm.y;
                    float asv = bsv + vs.x + vs.y;
                    float sn  = softplusf_(asv);

                    prmp[(size_t)i * 64] = __float2half(amv);
                    prsp[(size_t)i * 64] = __float2half(sn);
                    pmh[su][pp ^ 1][s] = __float2half(amv);
                }
                __syncthreads();
                pp ^= 1;
            }
        }
    }
}

// ---------------------------------------------------------------------------
// FUSED heads+KL+gen (+final combine): grid 1024, 256 thr, 128 bt-rows/block.
__global__ __launch_bounds__(256) void k_headsgen(
        const float* __restrict__ brm, const float* __restrict__ brs,
        const float* __restrict__ obs, const float* __restrict__ bgm,
        const float* __restrict__ bgs, float* __restrict__ out) {
    extern __shared__ __half sm[];
    __half* As = sm;                 // phase A: [128][136] hs tile
    __half* Bt = sm + 128 * 136;     // phase A: [128][136] WrT
    __half* pmA = sm;                // phase C: [128][72] pm tile
    __half* WgT = sm + 128 * 72;     // phase C: [256][72]
    __shared__ float red[8];
    const int tid = threadIdx.x;
    const int bt0 = blockIdx.x * 128;

    // ---- Phase A: heads GEMM ----
    const uint4* ap = (const uint4*)(g_hsh + (size_t)bt0 * 128);
    const uint4* bp = (const uint4*)g_WrTh;
    #pragma unroll
    for (int i = tid; i < 128 * 16; i += 256) {
        int r = i >> 4, c = i & 15;
        *(uint4*)&As[r * 136 + c * 8] = ap[r * 16 + c];
        *(uint4*)&Bt[r * 136 + c * 8] = bp[r * 16 + c];
    }
    __syncthreads();

    const int w = tid >> 5, l = tid & 31, g = l >> 2, tg = l & 3;
    const int m0 = w * 16;
    {
        float acc[16][4];
        #pragma unroll
        for (int i = 0; i < 16; i++)
            #pragma unroll
            for (int j = 0; j < 4; j++) acc[i][j] = 0.f;

        #pragma unroll
        for (int kk = 0; kk < 8; kk++) {
            const int kb = kk * 16 + tg * 2;
            unsigned a[4];
            a[0] = *(const unsigned*)&As[(m0 + g)     * 136 + kb];
            a[1] = *(const unsigned*)&As[(m0 + g + 8) * 136 + kb];
            a[2] = *(const unsigned*)&As[(m0 + g)     * 136 + kb + 8];
            a[3] = *(const unsigned*)&As[(m0 + g + 8) * 136 + kb + 8];
            #pragma unroll
            for (int na = 0; na < 16; na++) {
                unsigned b[2];
                b[0] = *(const unsigned*)&Bt[(na * 8 + g) * 136 + kb];
                b[1] = *(const unsigned*)&Bt[(na * 8 + g) * 136 + kb + 8];
                mma16816(acc[na], a, b);
            }
        }
        __syncthreads();             // all As/Bt reads done; safe to overwrite

        // ---- Phase B: KL (elementwise) + pm stage into smem ----
        float klsum = 0.f;
        #pragma unroll
        for (int na = 0; na < 8; na++) {
            int s0 = na * 8 + tg * 2;
            int lr0 = m0 + g, lr1 = lr0 + 8;
            int r0 = bt0 + lr0, r1 = bt0 + lr1;
            float2 bm = *(const float2*)&brm[s0];
            float2 bs = *(const float2*)&brs[s0];
            float pm00 = acc[na][0] + bm.x, pm01 = acc[na][1] + bm.y;
            float pm10 = acc[na][2] + bm.x, pm11 = acc[na][3] + bm.y;
            float sp00 = softplusf_(acc[na + 8][0] + bs.x);
            float sp01 = softplusf_(acc[na + 8][1] + bs.y);
            float sp10 = softplusf_(acc[na + 8][2] + bs.x);
            float sp11 = softplusf_(acc[na + 8][3] + bs.y);
            *(half2*)&pmA[lr0 * 72 + s0] = __floats2half2_rn(pm00, pm01);
            *(half2*)&pmA[lr1 * 72 + s0] = __floats2half2_rn(pm10, pm11);
            float2 am0 = __half22float2(*(const half2*)&g_prm[(size_t)r0 * 64 + s0]);
            float2 am1 = __half22float2(*(const half2*)&g_prm[(size_t)r1 * 64 + s0]);
            float2 sn0 = __half22float2(*(const half2*)&g_prs[(size_t)r0 * 64 + s0]);
            float2 sn1 = __half22float2(*(const half2*)&g_prs[(size_t)r1 * 64 + s0]);
            float d;
            d = pm00 - am0.x;
            klsum += __logf(__fdividef(sn0.x, sp00))
                   + __fdividef(sp00 * sp00 + d * d, 2.f * sn0.x * sn0.x) - 0.5f;
            d = pm01 - am0.y;
            klsum += __logf(__fdividef(sn0.y, sp01))
                   + __fdividef(sp01 * sp01 + d * d, 2.f * sn0.y * sn0.y) - 0.5f;
            d = pm10 - am1.x;
            klsum += __logf(__fdividef(sn1.x, sp10))
                   + __fdividef(sp10 * sp10 + d * d, 2.f * sn1.x * sn1.x) - 0.5f;
            d = pm11 - am1.y;
            klsum += __logf(__fdividef(sn1.y, sp11))
                   + __fdividef(sp11 * sp11 + d * d, 2.f * sn1.y * sn1.y) - 0.5f;
        }
        #pragma unroll
        for (int off = 16; off; off >>= 1)
            klsum += __shfl_down_sync(0xffffffffu, klsum, off);
        if (l == 0) red[w] = klsum;
        __syncthreads();
        if (tid == 0) {
            float s = 0.f;
            #pragma unroll
            for (int i = 0; i < 8; i++) s += red[i];
            atomicAdd(&g_acc[0], (double)s);
        }
    }
    // load WgT [256][64] -> smem [256][72]
    const uint4* gp = (const uint4*)g_WgTh;
    #pragma unroll
    for (int i = tid; i < 256 * 8; i += 256) {
        int r = i >> 3, c = i & 7;
        *(uint4*)&WgT[r * 72 + c * 8] = gp[i];
    }
    __syncthreads();

    // ---- Phase C: gen GEMM + recon ----
    float lsum = 0.f;
    #pragma unroll 1
    for (int ch = 0; ch < 2; ch++) {
        float am[8][4], as_[8][4];
        #pragma unroll
        for (int i = 0; i < 8; i++)
            #pragma unroll
            for (int j = 0; j < 4; j++) { am[i][j] = 0.f; as_[i][j] = 0.f; }

        #pragma unroll
        for (int kk = 0; kk < 4; kk++) {
            const int kb = kk * 16 + tg * 2;
            unsigned a[4];
            a[0] = *(const unsigned*)&pmA[(m0 + g)     * 72 + kb];
            a[1] = *(const unsigned*)&pmA[(m0 + g + 8) * 72 + kb];
            a[2] = *(const unsigned*)&pmA[(m0 + g)     * 72 + kb + 8];
            a[3] = *(const unsigned*)&pmA[(m0 + g + 8) * 72 + kb + 8];
            #pragma unroll
            for (int na = 0; na < 8; na++) {
                int nmu = ch * 64 + na * 8 + g;
                unsigned b[2], b2[2];
                b[0]  = *(const unsigned*)&WgT[nmu * 72 + kb];
                b[1]  = *(const unsigned*)&WgT[nmu * 72 + kb + 8];
                b2[0] = *(const unsigned*)&WgT[(nmu + 128) * 72 + kb];
                b2[1] = *(const unsigned*)&WgT[(nmu + 128) * 72 + kb + 8];
                mma16816(am[na], a, b);
                mma16816(as_[na], a, b2);
            }
        }
        #pragma unroll
        for (int na = 0; na < 8; na++) {
            int oc = ch * 64 + na * 8 + tg * 2;
            float2 bm2 = *(const float2*)&bgm[oc];
            float2 bs2 = *(const float2*)&bgs[oc];
            int r0 = bt0 + m0 + g, r1 = r0 + 8;
            float2 o0 = *(const float2*)&obs[(size_t)r0 * 128 + oc];
            float2 o1 = *(const float2*)&obs[(size_t)r1 * 128 + oc];
            float mu, sg, d;
            mu = am[na][0] + bm2.x; sg = softplusf_(as_[na][0] + bs2.x);
            d = __fdividef(o0.x - mu, sg); lsum += -0.5f * d * d - __logf(sg);
            mu = am[na][1] + bm2.y; sg = softplusf_(as_[na][1] + bs2.y);
            d = __fdividef(o0.y - mu, sg); lsum += -0.5f * d * d - __logf(sg);
            mu = am[na][2] + bm2.x; sg = softplusf_(as_[na][2] + bs2.x);
            d = __fdividef(o1.x - mu, sg); lsum += -0.5f * d * d - __logf(sg);
            mu = am[na][3] + bm2.y; sg = softplusf_(as_[na][3] + bs2.y);
            d = __fdividef(o1.y - mu, sg); lsum += -0.5f * d * d - __logf(sg);
        }
    }
    lsum -= 64.f * 0.91893853320467274f;   // 64 elements x 0.5*log(2pi)

    #pragma unroll
    for (int off = 16; off; off >>= 1) lsum += __shfl_down_sync(0xffffffffu, lsum, off);
    if (l == 0) red[w] = lsum;
    __syncthreads();
    if (tid == 0) {
        float s = 0.f;
        #pragma unroll
        for (int i = 0; i < 8; i++) s += red[i];
        atomicAdd(&g_acc[1], (double)s);
        __threadfence();
        unsigned old = atomicAdd(&g_done, 1u);
        if (old == gridDim.x - 1) {          // last block: final combine
            double kl = atomicAdd(&g_acc[0], 0.0);
            double rc = atomicAdd(&g_acc[1], 0.0);
            out[0] = (float)(kl / (double)BT_ - rc / (double)B_);
        }
    }
}

// ---------------------------------------------------------------------------
extern "C" void kernel_launch(void* const* d_in, const int* in_sizes, int n_in,
                              void* d_out, int out_size) {
    const float* obs = (const float*)d_in[0];
    const float* im  = (const float*)d_in[1];
    // d_in[2] = initial_scale (unused by the reference computation)
    const float* Wfm = (const float*)d_in[3];
    const float* bfm = (const float*)d_in[4];
    const float* Wfs = (const float*)d_in[5];
    const float* bfs = (const float*)d_in[6];
    const float* Wgm = (const float*)d_in[7];
    const float* bgm = (const float*)d_in[8];
    const float* Wgs = (const float*)d_in[9];
    const float* bgs = (const float*)d_in[10];
    const float* K   = (const float*)d_in[11];
    const float* R   = (const float*)d_in[12];
    const float* bl  = (const float*)d_in[13];
    const float* Wrm = (const float*)d_in[14];
    const float* brm = (const float*)d_in[15];
    const float* Wrs = (const float*)d_in[16];
    const float* brs = (const float*)d_in[17];
    float* out = (float*)d_out;

    const int GEMM_SM = 2 * 128 * 136 * 2;              // 69632
    const int PW_SM   = 3 * PW_N * PW_LD * 4;           // 53040
    cudaFuncSetAttribute(k_xk,       cudaFuncAttributeMaxDynamicSharedMemorySize, GEMM_SM);
    cudaFuncSetAttribute(k_headsgen, cudaFuncAttributeMaxDynamicSharedMemorySize, GEMM_SM);
    cudaFuncSetAttribute(k_prep,     cudaFuncAttributeMaxDynamicSharedMemorySize, PW_SM);

    k_prep<<<129, 256, PW_SM>>>(K, Wrm, Wrs, Wgm, Wgs, Wfm, bfm);
    k_xk<<<dim3(4, 1024), 256, GEMM_SM>>>(obs, bl);
    k_lstm<<<148, 512>>>(R, im, Wfm, bfm, Wfs, bfs);
    k_headsgen<<<1024, 256, GEMM_SM>>>(brm, brs, obs, bgm, bgs, out);
}